// round 3
// baseline (speedup 1.0000x reference)
#include <cuda_runtime.h>
#include <cuda_bf16.h>
#include <cstddef>

#define NN_MAX 50000
#define EE_MAX 1600000

// -------- scratch (device globals; no allocation allowed) --------
__device__ __align__(16) float g_dis[NN_MAX];        // 1/sqrt(1+in_deg)
__device__ int   g_cnt[NN_MAX];        // in-degree histogram
__device__ int   g_cur[NN_MAX];        // CSR fill cursors
__device__ int   g_off[NN_MAX + 1];    // CSR row offsets
__device__ int   g_csr[EE_MAX];        // src ids grouped by dst
__device__ __align__(16) float g_h[(size_t)NN_MAX * 128];   // post-GEMM features
__device__ __align__(16) float g_a[(size_t)NN_MAX * 128];   // post-agg activations
__device__ float g_t[NN_MAX];          // final-layer scalar projection

// ---------------- graph preprocessing ----------------
__global__ void zero_cnt_k(int n) {
    int i = blockIdx.x * blockDim.x + threadIdx.x;
    if (i < n) g_cnt[i] = 0;
}

// edge_index is INT32 on the wire (JAX x64 disabled): ei[0:E]=src, ei[E:2E]=dst
__global__ void hist_dst_k(const int* __restrict__ ei, int E) {
    int e = blockIdx.x * blockDim.x + threadIdx.x;
    if (e < E) atomicAdd(&g_cnt[ei[E + e]], 1);
}

// single block: exclusive scan of g_cnt -> g_off/g_cur; g_dis = rsqrt(1+cnt)
__global__ void scan_k(int n) {
    __shared__ int partial[1024];
    int tid = threadIdx.x;
    int chunk = (n + 1023) / 1024;
    int beg = tid * chunk;
    int end = min(beg + chunk, n);
    int s = 0;
    for (int i = beg; i < end; i++) s += g_cnt[i];
    partial[tid] = s;
    __syncthreads();
    // Hillis-Steele inclusive scan
    for (int d = 1; d < 1024; d <<= 1) {
        int v = (tid >= d) ? partial[tid - d] : 0;
        __syncthreads();
        partial[tid] += v;
        __syncthreads();
    }
    int run = (tid == 0) ? 0 : partial[tid - 1];
    for (int i = beg; i < end; i++) {
        g_off[i] = run;
        g_cur[i] = run;
        int c = g_cnt[i];
        run += c;
        g_dis[i] = rsqrtf(1.0f + (float)c);
    }
    if (tid == 0) g_off[n] = partial[1023];
}

__global__ void build_csr_k(const int* __restrict__ ei, int E) {
    int e = blockIdx.x * blockDim.x + threadIdx.x;
    if (e >= E) return;
    int s = ei[e];
    int d = ei[E + e];
    int p = atomicAdd(&g_cur[d], 1);
    g_csr[p] = s;
}

// ---------------- GEMM: g_h[M,128] = A[M,128] @ W[128,128] ----------------
// A = external input x if use_ga==0, else internal g_a.
// block: 64 rows, 256 threads; thread micro-tile = 4 rows x 8 cols
__global__ void gemm128_k(const float* __restrict__ Ax, const float* __restrict__ W,
                          int M, int use_ga)
{
    __shared__ float As[64][36];    // padded: conflict-free scalar reads
    __shared__ float Ws[32][128];

    const float* __restrict__ A = use_ga ? (const float*)g_a : Ax;
    float* __restrict__ C = g_h;

    int tid = threadIdx.x;
    int tx = tid & 15;              // col group: cols tx*8 .. tx*8+7
    int ty = tid >> 4;              // row group: rows ty*4 .. ty*4+3
    int row0 = blockIdx.x * 64;

    float acc[4][8];
#pragma unroll
    for (int i = 0; i < 4; i++)
#pragma unroll
        for (int j = 0; j < 8; j++) acc[i][j] = 0.f;

    for (int kb = 0; kb < 128; kb += 32) {
        // load A chunk: 64 rows x 32 cols = 512 float4
#pragma unroll
        for (int l = 0; l < 2; l++) {
            int idx = tid + l * 256;        // 0..511
            int r = idx >> 3;
            int c4 = idx & 7;
            int gr = row0 + r;
            if (gr > M - 1) gr = M - 1;     // clamp (tail rows unused)
            float4 v = *(const float4*)(A + (size_t)gr * 128 + kb + c4 * 4);
            *(float4*)(&As[r][c4 * 4]) = v;
        }
        // load W chunk: 32 rows x 128 cols = 1024 float4
#pragma unroll
        for (int l = 0; l < 4; l++) {
            int idx = tid + l * 256;        // 0..1023
            int r = idx >> 5;
            int c4 = idx & 31;
            float4 v = *(const float4*)(W + (size_t)(kb + r) * 128 + c4 * 4);
            *(float4*)(&Ws[r][c4 * 4]) = v;
        }
        __syncthreads();
#pragma unroll
        for (int k = 0; k < 32; k++) {
            float av[4];
#pragma unroll
            for (int i = 0; i < 4; i++) av[i] = As[ty * 4 + i][k];
            float4 w0 = *(float4*)(&Ws[k][tx * 8]);
            float4 w1 = *(float4*)(&Ws[k][tx * 8 + 4]);
            float wv[8] = {w0.x, w0.y, w0.z, w0.w, w1.x, w1.y, w1.z, w1.w};
#pragma unroll
            for (int i = 0; i < 4; i++)
#pragma unroll
                for (int j = 0; j < 8; j++)
                    acc[i][j] += av[i] * wv[j];
        }
        __syncthreads();
    }
#pragma unroll
    for (int i = 0; i < 4; i++) {
        int r = row0 + ty * 4 + i;
        if (r < M) {
            float4 o0 = {acc[i][0], acc[i][1], acc[i][2], acc[i][3]};
            float4 o1 = {acc[i][4], acc[i][5], acc[i][6], acc[i][7]};
            *(float4*)(C + (size_t)r * 128 + tx * 8)     = o0;
            *(float4*)(C + (size_t)r * 128 + tx * 8 + 4) = o1;
        }
    }
}

// ---------------- aggregation: warp per node, lane = float4 of row ----------------
// reads g_h, writes g_a
__global__ void agg128_k(const float* __restrict__ b, int M, int do_relu)
{
    int w = (blockIdx.x * blockDim.x + threadIdx.x) >> 5;
    if (w >= M) return;
    int lane = threadIdx.x & 31;
    const float* __restrict__ h = g_h;
    int beg = g_off[w], end = g_off[w + 1];
    float dv = g_dis[w];

    float ax = 0.f, ay = 0.f, az = 0.f, aw = 0.f;
    int e = beg;
    for (; e + 4 <= end; e += 4) {
        int s0 = g_csr[e], s1 = g_csr[e + 1], s2 = g_csr[e + 2], s3 = g_csr[e + 3];
        float w0 = g_dis[s0], w1 = g_dis[s1], w2 = g_dis[s2], w3 = g_dis[s3];
        float4 h0 = ((const float4*)(h + (size_t)s0 * 128))[lane];
        float4 h1 = ((const float4*)(h + (size_t)s1 * 128))[lane];
        float4 h2 = ((const float4*)(h + (size_t)s2 * 128))[lane];
        float4 h3 = ((const float4*)(h + (size_t)s3 * 128))[lane];
        ax += w0 * h0.x + w1 * h1.x + w2 * h2.x + w3 * h3.x;
        ay += w0 * h0.y + w1 * h1.y + w2 * h2.y + w3 * h3.y;
        az += w0 * h0.z + w1 * h1.z + w2 * h2.z + w3 * h3.z;
        aw += w0 * h0.w + w1 * h1.w + w2 * h2.w + w3 * h3.w;
    }
    for (; e < end; e++) {
        int s0 = g_csr[e];
        float w0 = g_dis[s0];
        float4 h0 = ((const float4*)(h + (size_t)s0 * 128))[lane];
        ax += w0 * h0.x; ay += w0 * h0.y; az += w0 * h0.z; aw += w0 * h0.w;
    }

    float4 hs = ((const float4*)(h + (size_t)w * 128))[lane];
    float4 bb = ((const float4*)b)[lane];
    float ns = dv * dv;
    float rx = dv * ax + ns * hs.x + bb.x;
    float ry = dv * ay + ns * hs.y + bb.y;
    float rz = dv * az + ns * hs.z + bb.z;
    float rw = dv * aw + ns * hs.w + bb.w;
    if (do_relu) {
        rx = fmaxf(rx, 0.f); ry = fmaxf(ry, 0.f);
        rz = fmaxf(rz, 0.f); rw = fmaxf(rw, 0.f);
    }
    float4 o = {rx, ry, rz, rw};
    ((float4*)(g_a + (size_t)w * 128))[lane] = o;
}

// ---------------- final layer: t[v] = g_a[v] . W4 (128 -> 1) ----------------
__global__ void dot_w4_k(const float* __restrict__ W4, int M)
{
    int w = (blockIdx.x * blockDim.x + threadIdx.x) >> 5;
    if (w >= M) return;
    int lane = threadIdx.x & 31;
    float4 a = ((const float4*)(g_a + (size_t)w * 128))[lane];
    float4 b = ((const float4*)W4)[lane];
    float s = a.x * b.x + a.y * b.y + a.z * b.z + a.w * b.w;
#pragma unroll
    for (int o = 16; o; o >>= 1) s += __shfl_xor_sync(0xFFFFFFFFu, s, o);
    if (lane == 0) g_t[w] = s;
}

__global__ void final_agg_k(const float* __restrict__ b4, float* __restrict__ out, int M)
{
    int v = blockIdx.x * blockDim.x + threadIdx.x;
    if (v >= M) return;
    float dv = g_dis[v];
    int beg = g_off[v], end = g_off[v + 1];
    float s = 0.f;
    for (int e = beg; e < end; e++) {
        int u = g_csr[e];
        s += g_t[u] * g_dis[u];
    }
    out[v] = dv * s + dv * dv * g_t[v] + b4[0];
}

// ---------------- launch ----------------
extern "C" void kernel_launch(void* const* d_in, const int* in_sizes, int n_in,
                              void* d_out, int out_size)
{
    const float* x  = (const float*)d_in[0];
    const int*   ei = (const int*)d_in[1];      // int32 on the wire (JAX x64 off)
    const float* W1 = (const float*)d_in[2]; const float* b1 = (const float*)d_in[3];
    const float* W2 = (const float*)d_in[4]; const float* b2 = (const float*)d_in[5];
    const float* W3 = (const float*)d_in[6]; const float* b3 = (const float*)d_in[7];
    const float* W4 = (const float*)d_in[8]; const float* b4 = (const float*)d_in[9];

    int N = in_sizes[0] / 128;   // 50000
    int E = in_sizes[1] / 2;     // 1600000
    float* out = (float*)d_out;

    // graph preprocessing (once per launch)
    zero_cnt_k <<<(N + 255) / 256, 256>>>(N);
    hist_dst_k <<<(E + 255) / 256, 256>>>(ei, E);
    scan_k     <<<1, 1024>>>(N);
    build_csr_k<<<(E + 255) / 256, 256>>>(ei, E);

    int gemm_blocks = (N + 63) / 64;
    int agg_blocks  = (N * 32 + 255) / 256;

    gemm128_k<<<gemm_blocks, 256>>>(x, W1, N, 0);
    agg128_k <<<agg_blocks, 256>>>(b1, N, 1);

    gemm128_k<<<gemm_blocks, 256>>>(x, W2, N, 1);
    agg128_k <<<agg_blocks, 256>>>(b2, N, 1);

    gemm128_k<<<gemm_blocks, 256>>>(x, W3, N, 1);
    agg128_k <<<agg_blocks, 256>>>(b3, N, 1);

    dot_w4_k   <<<(N * 32 + 255) / 256, 256>>>(W4, N);
    final_agg_k<<<(N + 255) / 256, 256>>>(b4, out, N);
}

// round 4
// speedup vs baseline: 1.3806x; 1.3806x over previous
#include <cuda_runtime.h>
#include <cuda_bf16.h>
#include <cstddef>

#define NN_MAX 50000
#define EE_MAX 1600000

// -------- scratch (device globals; no allocation allowed) --------
__device__ __align__(16) float g_dis[NN_MAX];        // 1/sqrt(1+in_deg)
__device__ int   g_cnt[NN_MAX];        // in-degree histogram
__device__ int   g_cur[NN_MAX];        // CSR fill cursors
__device__ int   g_off[NN_MAX + 1];    // CSR row offsets
__device__ int   g_csr[EE_MAX];        // src ids grouped by dst
__device__ __align__(16) float g_h[(size_t)NN_MAX * 128];   // post-GEMM features
__device__ __align__(16) float g_a[(size_t)NN_MAX * 128];   // post-agg activations
__device__ float g_t[NN_MAX];          // final-layer scalar projection

// ---------------- graph preprocessing ----------------
__global__ void zero_cnt_k(int n) {
    int i = blockIdx.x * blockDim.x + threadIdx.x;
    if (i < n) g_cnt[i] = 0;
}

// edge_index is INT32 on the wire: ei[0:E]=src, ei[E:2E]=dst
__global__ void hist_dst_k(const int* __restrict__ ei, int E) {
    int e = blockIdx.x * blockDim.x + threadIdx.x;
    if (e < E) atomicAdd(&g_cnt[ei[E + e]], 1);
}

// single block: exclusive scan of g_cnt -> g_off/g_cur; g_dis = rsqrt(1+cnt)
__global__ void scan_k(int n) {
    __shared__ int partial[1024];
    int tid = threadIdx.x;
    int chunk = (n + 1023) / 1024;
    int beg = tid * chunk;
    int end = min(beg + chunk, n);
    int s = 0;
    for (int i = beg; i < end; i++) s += g_cnt[i];
    partial[tid] = s;
    __syncthreads();
    for (int d = 1; d < 1024; d <<= 1) {
        int v = (tid >= d) ? partial[tid - d] : 0;
        __syncthreads();
        partial[tid] += v;
        __syncthreads();
    }
    int run = (tid == 0) ? 0 : partial[tid - 1];
    for (int i = beg; i < end; i++) {
        g_off[i] = run;
        g_cur[i] = run;
        int c = g_cnt[i];
        run += c;
        g_dis[i] = rsqrtf(1.0f + (float)c);
    }
    if (tid == 0) g_off[n] = partial[1023];
}

__global__ void build_csr_k(const int* __restrict__ ei, int E) {
    int e = blockIdx.x * blockDim.x + threadIdx.x;
    if (e >= E) return;
    int s = ei[e];
    int d = ei[E + e];
    int p = atomicAdd(&g_cur[d], 1);
    g_csr[p] = s;
}

// ---------------- TF32 tensor-core GEMM: g_h[M,128] = A[M,128] @ W[128,128] ----
// block tile 128x128, 256 threads = 8 warps (4 M x 2 N), warp tile 32x64.
// K chunked by 32 through smem; tf32 conversion at smem-store time.
__device__ __forceinline__ unsigned f2tf32(float f) {
    unsigned u;
    asm("cvt.rna.tf32.f32 %0, %1;" : "=r"(u) : "f"(f));
    return u;
}

__global__ __launch_bounds__(256, 2)
void gemm_tf32_k(const float* __restrict__ Ax, const float* __restrict__ W,
                 int M, int use_ga)
{
    // pad A rows to 36 (bank = 4g+tig distinct), B rows to 132 (bank = 4tig+g distinct)
    __shared__ unsigned As[128][36];
    __shared__ unsigned Bs[32][132];

    const float* __restrict__ A = use_ga ? (const float*)g_a : Ax;
    float* __restrict__ C = g_h;

    int tid  = threadIdx.x;
    int wid  = tid >> 5;
    int lane = tid & 31;
    int g    = lane >> 2;          // groupID 0..7
    int tig  = lane & 3;           // thread-in-group 0..3
    int warp_m = wid & 3;          // 0..3  -> rows warp_m*32
    int warp_n = wid >> 2;         // 0..1  -> cols warp_n*64
    int row0 = blockIdx.x * 128;

    float acc[2][8][4];
#pragma unroll
    for (int mf = 0; mf < 2; mf++)
#pragma unroll
        for (int nf = 0; nf < 8; nf++)
#pragma unroll
            for (int i = 0; i < 4; i++) acc[mf][nf][i] = 0.f;

    for (int kb = 0; kb < 128; kb += 32) {
        // load A chunk: 128 rows x 32 cols = 1024 float4 -> tf32
#pragma unroll
        for (int l = 0; l < 4; l++) {
            int idx = tid + l * 256;         // 0..1023
            int r  = idx >> 3;
            int c4 = idx & 7;
            int gr = row0 + r;
            if (gr > M - 1) gr = M - 1;
            float4 v = *(const float4*)(A + (size_t)gr * 128 + kb + c4 * 4);
            unsigned* d = &As[r][c4 * 4];
            d[0] = f2tf32(v.x); d[1] = f2tf32(v.y);
            d[2] = f2tf32(v.z); d[3] = f2tf32(v.w);
        }
        // load B chunk: 32 rows x 128 cols = 1024 float4 -> tf32
#pragma unroll
        for (int l = 0; l < 4; l++) {
            int idx = tid + l * 256;
            int r  = idx >> 5;
            int c4 = idx & 31;
            float4 v = *(const float4*)(W + (size_t)(kb + r) * 128 + c4 * 4);
            unsigned* d = &Bs[r][c4 * 4];
            d[0] = f2tf32(v.x); d[1] = f2tf32(v.y);
            d[2] = f2tf32(v.z); d[3] = f2tf32(v.w);
        }
        __syncthreads();

#pragma unroll
        for (int ks = 0; ks < 4; ks++) {
            int k0 = ks * 8;
            // A fragments (2 m-frags x 4 regs)
            unsigned a[2][4];
#pragma unroll
            for (int mf = 0; mf < 2; mf++) {
                int rb = warp_m * 32 + mf * 16 + g;
                a[mf][0] = As[rb][k0 + tig];
                a[mf][1] = As[rb + 8][k0 + tig];
                a[mf][2] = As[rb][k0 + tig + 4];
                a[mf][3] = As[rb + 8][k0 + tig + 4];
            }
            // B fragments (8 n-frags x 2 regs)
            unsigned b[8][2];
#pragma unroll
            for (int nf = 0; nf < 8; nf++) {
                int cb = warp_n * 64 + nf * 8 + g;
                b[nf][0] = Bs[k0 + tig][cb];
                b[nf][1] = Bs[k0 + tig + 4][cb];
            }
#pragma unroll
            for (int mf = 0; mf < 2; mf++)
#pragma unroll
                for (int nf = 0; nf < 8; nf++) {
                    asm volatile(
                        "mma.sync.aligned.m16n8k8.row.col.f32.tf32.tf32.f32 "
                        "{%0,%1,%2,%3}, {%4,%5,%6,%7}, {%8,%9}, {%0,%1,%2,%3};"
                        : "+f"(acc[mf][nf][0]), "+f"(acc[mf][nf][1]),
                          "+f"(acc[mf][nf][2]), "+f"(acc[mf][nf][3])
                        : "r"(a[mf][0]), "r"(a[mf][1]), "r"(a[mf][2]), "r"(a[mf][3]),
                          "r"(b[nf][0]), "r"(b[nf][1]));
                }
        }
        __syncthreads();
    }

    // epilogue: c0,c1 -> (row, col..col+1), c2,c3 -> (row+8, col..col+1)
#pragma unroll
    for (int mf = 0; mf < 2; mf++) {
        int rb = row0 + warp_m * 32 + mf * 16 + g;
#pragma unroll
        for (int nf = 0; nf < 8; nf++) {
            int col = warp_n * 64 + nf * 8 + tig * 2;
            if (rb < M) {
                float2 v = {acc[mf][nf][0], acc[mf][nf][1]};
                *(float2*)(C + (size_t)rb * 128 + col) = v;
            }
            if (rb + 8 < M) {
                float2 v = {acc[mf][nf][2], acc[mf][nf][3]};
                *(float2*)(C + (size_t)(rb + 8) * 128 + col) = v;
            }
        }
    }
}

// ---------------- aggregation: warp per node, lane = float4 of row ----------------
// reads g_h, writes g_a
__global__ void agg128_k(const float* __restrict__ b, int M, int do_relu)
{
    int w = (blockIdx.x * blockDim.x + threadIdx.x) >> 5;
    if (w >= M) return;
    int lane = threadIdx.x & 31;
    const float* __restrict__ h = g_h;
    int beg = g_off[w], end = g_off[w + 1];
    float dv = g_dis[w];

    float ax = 0.f, ay = 0.f, az = 0.f, aw = 0.f;
    int e = beg;
    for (; e + 4 <= end; e += 4) {
        int s0 = g_csr[e], s1 = g_csr[e + 1], s2 = g_csr[e + 2], s3 = g_csr[e + 3];
        float w0 = g_dis[s0], w1 = g_dis[s1], w2 = g_dis[s2], w3 = g_dis[s3];
        float4 h0 = ((const float4*)(h + (size_t)s0 * 128))[lane];
        float4 h1 = ((const float4*)(h + (size_t)s1 * 128))[lane];
        float4 h2 = ((const float4*)(h + (size_t)s2 * 128))[lane];
        float4 h3 = ((const float4*)(h + (size_t)s3 * 128))[lane];
        ax += w0 * h0.x + w1 * h1.x + w2 * h2.x + w3 * h3.x;
        ay += w0 * h0.y + w1 * h1.y + w2 * h2.y + w3 * h3.y;
        az += w0 * h0.z + w1 * h1.z + w2 * h2.z + w3 * h3.z;
        aw += w0 * h0.w + w1 * h1.w + w2 * h2.w + w3 * h3.w;
    }
    for (; e < end; e++) {
        int s0 = g_csr[e];
        float w0 = g_dis[s0];
        float4 h0 = ((const float4*)(h + (size_t)s0 * 128))[lane];
        ax += w0 * h0.x; ay += w0 * h0.y; az += w0 * h0.z; aw += w0 * h0.w;
    }

    float4 hs = ((const float4*)(h + (size_t)w * 128))[lane];
    float4 bb = ((const float4*)b)[lane];
    float ns = dv * dv;
    float rx = dv * ax + ns * hs.x + bb.x;
    float ry = dv * ay + ns * hs.y + bb.y;
    float rz = dv * az + ns * hs.z + bb.z;
    float rw = dv * aw + ns * hs.w + bb.w;
    if (do_relu) {
        rx = fmaxf(rx, 0.f); ry = fmaxf(ry, 0.f);
        rz = fmaxf(rz, 0.f); rw = fmaxf(rw, 0.f);
    }
    float4 o = {rx, ry, rz, rw};
    ((float4*)(g_a + (size_t)w * 128))[lane] = o;
}

// ---------------- final layer: t[v] = g_a[v] . W4 (128 -> 1) ----------------
__global__ void dot_w4_k(const float* __restrict__ W4, int M)
{
    int w = (blockIdx.x * blockDim.x + threadIdx.x) >> 5;
    if (w >= M) return;
    int lane = threadIdx.x & 31;
    float4 a = ((const float4*)(g_a + (size_t)w * 128))[lane];
    float4 b = ((const float4*)W4)[lane];
    float s = a.x * b.x + a.y * b.y + a.z * b.z + a.w * b.w;
#pragma unroll
    for (int o = 16; o; o >>= 1) s += __shfl_xor_sync(0xFFFFFFFFu, s, o);
    if (lane == 0) g_t[w] = s;
}

__global__ void final_agg_k(const float* __restrict__ b4, float* __restrict__ out, int M)
{
    int v = blockIdx.x * blockDim.x + threadIdx.x;
    if (v >= M) return;
    float dv = g_dis[v];
    int beg = g_off[v], end = g_off[v + 1];
    float s = 0.f;
    for (int e = beg; e < end; e++) {
        int u = g_csr[e];
        s += g_t[u] * g_dis[u];
    }
    out[v] = dv * s + dv * dv * g_t[v] + b4[0];
}

// ---------------- launch ----------------
extern "C" void kernel_launch(void* const* d_in, const int* in_sizes, int n_in,
                              void* d_out, int out_size)
{
    const float* x  = (const float*)d_in[0];
    const int*   ei = (const int*)d_in[1];      // int32 on the wire
    const float* W1 = (const float*)d_in[2]; const float* b1 = (const float*)d_in[3];
    const float* W2 = (const float*)d_in[4]; const float* b2 = (const float*)d_in[5];
    const float* W3 = (const float*)d_in[6]; const float* b3 = (const float*)d_in[7];
    const float* W4 = (const float*)d_in[8]; const float* b4 = (const float*)d_in[9];

    int N = in_sizes[0] / 128;   // 50000
    int E = in_sizes[1] / 2;     // 1600000
    float* out = (float*)d_out;

    // graph preprocessing (once per launch)
    zero_cnt_k <<<(N + 255) / 256, 256>>>(N);
    hist_dst_k <<<(E + 255) / 256, 256>>>(ei, E);
    scan_k     <<<1, 1024>>>(N);
    build_csr_k<<<(E + 255) / 256, 256>>>(ei, E);

    int gemm_blocks = (N + 127) / 128;
    int agg_blocks  = (N * 32 + 255) / 256;

    gemm_tf32_k<<<gemm_blocks, 256>>>(x, W1, N, 0);
    agg128_k   <<<agg_blocks, 256>>>(b1, N, 1);

    gemm_tf32_k<<<gemm_blocks, 256>>>(x, W2, N, 1);
    agg128_k   <<<agg_blocks, 256>>>(b2, N, 1);

    gemm_tf32_k<<<gemm_blocks, 256>>>(x, W3, N, 1);
    agg128_k   <<<agg_blocks, 256>>>(b3, N, 1);

    dot_w4_k   <<<(N * 32 + 255) / 256, 256>>>(W4, N);
    final_agg_k<<<(N + 255) / 256, 256>>>(b4, out, N);
}

// round 5
// speedup vs baseline: 1.4628x; 1.0595x over previous
#include <cuda_runtime.h>
#include <cuda_fp16.h>
#include <cstddef>

#define NN_MAX 50000
#define EE_MAX 1600000

// -------- scratch (device globals; no allocation allowed) --------
__device__ __align__(16) float  g_dis[NN_MAX];      // 1/sqrt(1+in_deg)
__device__ int    g_cnt[NN_MAX];
__device__ int    g_cur[NN_MAX];
__device__ int    g_off[NN_MAX + 1];
__device__ int    g_csr[EE_MAX];
__device__ __align__(16) __half g_h16[(size_t)NN_MAX * 128];  // post-GEMM (fp16)
__device__ __align__(16) __half g_a16[(size_t)NN_MAX * 128];  // post-agg (fp16)
__device__ float  g_t[NN_MAX];                      // final scalar projection

// ---------------- helpers ----------------
__device__ __forceinline__ unsigned f2tf32(float f) {
    unsigned u;
    asm("cvt.rna.tf32.f32 %0, %1;" : "=r"(u) : "f"(f));
    return u;
}
__device__ __forceinline__ float4 h8_to_f4(float2 raw) {
    __half2 ha = *reinterpret_cast<__half2*>(&raw.x);
    __half2 hb = *reinterpret_cast<__half2*>(&raw.y);
    float2 fa = __half22float2(ha), fb = __half22float2(hb);
    return make_float4(fa.x, fa.y, fb.x, fb.y);
}
__device__ __forceinline__ float2 f4_to_h8(float x, float y, float z, float w) {
    __half2 h0 = __floats2half2_rn(x, y), h1 = __floats2half2_rn(z, w);
    float2 o;
    o.x = *reinterpret_cast<float*>(&h0);
    o.y = *reinterpret_cast<float*>(&h1);
    return o;
}

// ---------------- graph preprocessing ----------------
__global__ void zero_cnt_k(int n) {
    int i = blockIdx.x * blockDim.x + threadIdx.x;
    if (i < n) g_cnt[i] = 0;
}

__global__ void hist_dst_k(const int* __restrict__ ei, int E) {
    int e = blockIdx.x * blockDim.x + threadIdx.x;
    if (e < E) atomicAdd(&g_cnt[ei[E + e]], 1);
}

__global__ void scan_k(int n) {
    __shared__ int partial[1024];
    int tid = threadIdx.x;
    int chunk = (n + 1023) / 1024;
    int beg = tid * chunk;
    int end = min(beg + chunk, n);
    int s = 0;
    for (int i = beg; i < end; i++) s += g_cnt[i];
    partial[tid] = s;
    __syncthreads();
    for (int d = 1; d < 1024; d <<= 1) {
        int v = (tid >= d) ? partial[tid - d] : 0;
        __syncthreads();
        partial[tid] += v;
        __syncthreads();
    }
    int run = (tid == 0) ? 0 : partial[tid - 1];
    for (int i = beg; i < end; i++) {
        g_off[i] = run;
        g_cur[i] = run;
        int c = g_cnt[i];
        run += c;
        g_dis[i] = rsqrtf(1.0f + (float)c);
    }
    if (tid == 0) g_off[n] = partial[1023];
}

__global__ void build_csr_k(const int* __restrict__ ei, int E) {
    int e = blockIdx.x * blockDim.x + threadIdx.x;
    if (e >= E) return;
    int s = ei[e];
    int d = ei[E + e];
    int p = atomicAdd(&g_cur[d], 1);
    g_csr[p] = s;
}

// ---------------- TF32 tensor-core GEMM: g_h16[M,128] = A[M,128] @ W[128,128] --
// A = fp32 input x (use_ga==0) or fp16 g_a16 (use_ga==1).
// block tile 128x128, 8 warps (4Mx2N), warp tile 32x64, K chunked by 32.
__global__ __launch_bounds__(256, 2)
void gemm_tf32_k(const float* __restrict__ Ax, const float* __restrict__ W,
                 int M, int use_ga)
{
    __shared__ unsigned As[128][36];
    __shared__ unsigned Bs[32][132];

    int tid  = threadIdx.x;
    int wid  = tid >> 5;
    int lane = tid & 31;
    int g    = lane >> 2;
    int tig  = lane & 3;
    int warp_m = wid & 3;
    int warp_n = wid >> 2;
    int row0 = blockIdx.x * 128;

    float acc[2][8][4];
#pragma unroll
    for (int mf = 0; mf < 2; mf++)
#pragma unroll
        for (int nf = 0; nf < 8; nf++)
#pragma unroll
            for (int i = 0; i < 4; i++) acc[mf][nf][i] = 0.f;

    for (int kb = 0; kb < 128; kb += 32) {
        if (use_ga) {
            // fp16 A: 128 rows x 32 halves = 512 x 16B loads (8 halves each)
            const __half* A16 = g_a16;
#pragma unroll
            for (int l = 0; l < 2; l++) {
                int idx = tid + l * 256;          // 0..511
                int r  = idx >> 2;
                int c8 = idx & 3;
                int gr = row0 + r;
                if (gr > M - 1) gr = M - 1;
                float4 raw = *(const float4*)(A16 + (size_t)gr * 128 + kb + c8 * 8);
                float4 f0 = h8_to_f4(make_float2(raw.x, raw.y));
                float4 f1 = h8_to_f4(make_float2(raw.z, raw.w));
                unsigned* d = &As[r][c8 * 8];
                d[0] = f2tf32(f0.x); d[1] = f2tf32(f0.y);
                d[2] = f2tf32(f0.z); d[3] = f2tf32(f0.w);
                d[4] = f2tf32(f1.x); d[5] = f2tf32(f1.y);
                d[6] = f2tf32(f1.z); d[7] = f2tf32(f1.w);
            }
        } else {
            // fp32 A: 128 rows x 32 floats = 1024 float4
#pragma unroll
            for (int l = 0; l < 4; l++) {
                int idx = tid + l * 256;
                int r  = idx >> 3;
                int c4 = idx & 7;
                int gr = row0 + r;
                if (gr > M - 1) gr = M - 1;
                float4 v = *(const float4*)(Ax + (size_t)gr * 128 + kb + c4 * 4);
                unsigned* d = &As[r][c4 * 4];
                d[0] = f2tf32(v.x); d[1] = f2tf32(v.y);
                d[2] = f2tf32(v.z); d[3] = f2tf32(v.w);
            }
        }
        // W chunk: 32 rows x 128 cols = 1024 float4
#pragma unroll
        for (int l = 0; l < 4; l++) {
            int idx = tid + l * 256;
            int r  = idx >> 5;
            int c4 = idx & 31;
            float4 v = *(const float4*)(W + (size_t)(kb + r) * 128 + c4 * 4);
            unsigned* d = &Bs[r][c4 * 4];
            d[0] = f2tf32(v.x); d[1] = f2tf32(v.y);
            d[2] = f2tf32(v.z); d[3] = f2tf32(v.w);
        }
        __syncthreads();

#pragma unroll
        for (int ks = 0; ks < 4; ks++) {
            int k0 = ks * 8;
            unsigned a[2][4];
#pragma unroll
            for (int mf = 0; mf < 2; mf++) {
                int rb = warp_m * 32 + mf * 16 + g;
                a[mf][0] = As[rb][k0 + tig];
                a[mf][1] = As[rb + 8][k0 + tig];
                a[mf][2] = As[rb][k0 + tig + 4];
                a[mf][3] = As[rb + 8][k0 + tig + 4];
            }
            unsigned b[8][2];
#pragma unroll
            for (int nf = 0; nf < 8; nf++) {
                int cb = warp_n * 64 + nf * 8 + g;
                b[nf][0] = Bs[k0 + tig][cb];
                b[nf][1] = Bs[k0 + tig + 4][cb];
            }
#pragma unroll
            for (int mf = 0; mf < 2; mf++)
#pragma unroll
                for (int nf = 0; nf < 8; nf++) {
                    asm volatile(
                        "mma.sync.aligned.m16n8k8.row.col.f32.tf32.tf32.f32 "
                        "{%0,%1,%2,%3}, {%4,%5,%6,%7}, {%8,%9}, {%0,%1,%2,%3};"
                        : "+f"(acc[mf][nf][0]), "+f"(acc[mf][nf][1]),
                          "+f"(acc[mf][nf][2]), "+f"(acc[mf][nf][3])
                        : "r"(a[mf][0]), "r"(a[mf][1]), "r"(a[mf][2]), "r"(a[mf][3]),
                          "r"(b[nf][0]), "r"(b[nf][1]));
                }
        }
        __syncthreads();
    }

    // epilogue: write fp16
#pragma unroll
    for (int mf = 0; mf < 2; mf++) {
        int rb = row0 + warp_m * 32 + mf * 16 + g;
#pragma unroll
        for (int nf = 0; nf < 8; nf++) {
            int col = warp_n * 64 + nf * 8 + tig * 2;
            if (rb < M) {
                __half2 v = __floats2half2_rn(acc[mf][nf][0], acc[mf][nf][1]);
                *(__half2*)(g_h16 + (size_t)rb * 128 + col) = v;
            }
            if (rb + 8 < M) {
                __half2 v = __floats2half2_rn(acc[mf][nf][2], acc[mf][nf][3]);
                *(__half2*)(g_h16 + (size_t)(rb + 8) * 128 + col) = v;
            }
        }
    }
}

// ---------------- aggregation: warp per node, lane = 4 consecutive features ----
// reads g_h16; writes g_a16 (relu); if W4 != null, instead writes g_t[w] = relu_out . W4
__global__ void agg128_k(const float* __restrict__ b, int M,
                         const float* __restrict__ W4)
{
    int w = (blockIdx.x * blockDim.x + threadIdx.x) >> 5;
    if (w >= M) return;
    int lane = threadIdx.x & 31;
    const __half* __restrict__ h = g_h16;
    int beg = g_off[w], end = g_off[w + 1];
    float dv = g_dis[w];

    float ax = 0.f, ay = 0.f, az = 0.f, aw = 0.f;
    int e = beg;
    for (; e + 4 <= end; e += 4) {
        int s0 = g_csr[e], s1 = g_csr[e + 1], s2 = g_csr[e + 2], s3 = g_csr[e + 3];
        float w0 = g_dis[s0], w1 = g_dis[s1], w2 = g_dis[s2], w3 = g_dis[s3];
        float2 r0 = ((const float2*)(h + (size_t)s0 * 128))[lane];
        float2 r1 = ((const float2*)(h + (size_t)s1 * 128))[lane];
        float2 r2 = ((const float2*)(h + (size_t)s2 * 128))[lane];
        float2 r3 = ((const float2*)(h + (size_t)s3 * 128))[lane];
        float4 h0 = h8_to_f4(r0), h1 = h8_to_f4(r1);
        float4 h2 = h8_to_f4(r2), h3 = h8_to_f4(r3);
        ax += w0 * h0.x + w1 * h1.x + w2 * h2.x + w3 * h3.x;
        ay += w0 * h0.y + w1 * h1.y + w2 * h2.y + w3 * h3.y;
        az += w0 * h0.z + w1 * h1.z + w2 * h2.z + w3 * h3.z;
        aw += w0 * h0.w + w1 * h1.w + w2 * h2.w + w3 * h3.w;
    }
    for (; e < end; e++) {
        int s0 = g_csr[e];
        float w0 = g_dis[s0];
        float4 h0 = h8_to_f4(((const float2*)(h + (size_t)s0 * 128))[lane]);
        ax += w0 * h0.x; ay += w0 * h0.y; az += w0 * h0.z; aw += w0 * h0.w;
    }

    float4 hs = h8_to_f4(((const float2*)(h + (size_t)w * 128))[lane]);
    float4 bb = ((const float4*)b)[lane];
    float ns = dv * dv;
    float rx = fmaxf(dv * ax + ns * hs.x + bb.x, 0.f);
    float ry = fmaxf(dv * ay + ns * hs.y + bb.y, 0.f);
    float rz = fmaxf(dv * az + ns * hs.z + bb.z, 0.f);
    float rw = fmaxf(dv * aw + ns * hs.w + bb.w, 0.f);

    if (W4 == nullptr) {
        ((float2*)(g_a16 + (size_t)w * 128))[lane] = f4_to_h8(rx, ry, rz, rw);
    } else {
        float4 wv = ((const float4*)W4)[lane];
        float s = rx * wv.x + ry * wv.y + rz * wv.z + rw * wv.w;
#pragma unroll
        for (int o = 16; o; o >>= 1) s += __shfl_xor_sync(0xFFFFFFFFu, s, o);
        if (lane == 0) g_t[w] = s;
    }
}

__global__ void final_agg_k(const float* __restrict__ b4, float* __restrict__ out, int M)
{
    int v = blockIdx.x * blockDim.x + threadIdx.x;
    if (v >= M) return;
    float dv = g_dis[v];
    int beg = g_off[v], end = g_off[v + 1];
    float s = 0.f;
    for (int e = beg; e < end; e++) {
        int u = g_csr[e];
        s += g_t[u] * g_dis[u];
    }
    out[v] = dv * s + dv * dv * g_t[v] + b4[0];
}

// ---------------- launch ----------------
extern "C" void kernel_launch(void* const* d_in, const int* in_sizes, int n_in,
                              void* d_out, int out_size)
{
    const float* x  = (const float*)d_in[0];
    const int*   ei = (const int*)d_in[1];      // int32 on the wire
    const float* W1 = (const float*)d_in[2]; const float* b1 = (const float*)d_in[3];
    const float* W2 = (const float*)d_in[4]; const float* b2 = (const float*)d_in[5];
    const float* W3 = (const float*)d_in[6]; const float* b3 = (const float*)d_in[7];
    const float* W4 = (const float*)d_in[8]; const float* b4 = (const float*)d_in[9];

    int N = in_sizes[0] / 128;   // 50000
    int E = in_sizes[1] / 2;     // 1600000
    float* out = (float*)d_out;

    // graph preprocessing
    zero_cnt_k <<<(N + 255) / 256, 256>>>(N);
    hist_dst_k <<<(E + 255) / 256, 256>>>(ei, E);
    scan_k     <<<1, 1024>>>(N);
    build_csr_k<<<(E + 255) / 256, 256>>>(ei, E);

    int gemm_blocks = (N + 127) / 128;
    int agg_blocks  = (N * 32 + 255) / 256;

    gemm_tf32_k<<<gemm_blocks, 256>>>(x, W1, N, 0);
    agg128_k   <<<agg_blocks, 256>>>(b1, N, nullptr);

    gemm_tf32_k<<<gemm_blocks, 256>>>(x, W2, N, 1);
    agg128_k   <<<agg_blocks, 256>>>(b2, N, nullptr);

    gemm_tf32_k<<<gemm_blocks, 256>>>(x, W3, N, 1);
    agg128_k   <<<agg_blocks, 256>>>(b3, N, W4);   // fused relu + dot(W4) -> g_t

    final_agg_k<<<(N + 255) / 256, 256>>>(b4, out, N);
}

// round 6
// speedup vs baseline: 1.6477x; 1.1264x over previous
#include <cuda_runtime.h>
#include <cuda_fp16.h>
#include <cstddef>

#define NN_MAX 50000
#define EE_MAX 1600000

// -------- scratch (device globals; no allocation allowed) --------
__device__ __align__(16) float  g_dis[NN_MAX];      // 1/sqrt(1+in_deg)
__device__ int    g_cnt[NN_MAX];
__device__ int    g_cur[NN_MAX];
__device__ int    g_off[NN_MAX + 1];
__device__ __align__(16) int g_csr[EE_MAX];
__device__ __align__(16) __half g_h16[(size_t)NN_MAX * 128];  // post-GEMM, PRE-SCALED by dis[row]
__device__ __align__(16) __half g_a16[(size_t)NN_MAX * 128];  // post-agg activations (plain)
__device__ float  g_t[NN_MAX];                      // final scalar projection, PRE-SCALED by dis

// ---------------- helpers ----------------
__device__ __forceinline__ unsigned f2tf32(float f) {
    unsigned u;
    asm("cvt.rna.tf32.f32 %0, %1;" : "=r"(u) : "f"(f));
    return u;
}
__device__ __forceinline__ float4 h8_to_f4(float2 raw) {
    __half2 ha = *reinterpret_cast<__half2*>(&raw.x);
    __half2 hb = *reinterpret_cast<__half2*>(&raw.y);
    float2 fa = __half22float2(ha), fb = __half22float2(hb);
    return make_float4(fa.x, fa.y, fb.x, fb.y);
}
__device__ __forceinline__ float2 f4_to_h8(float x, float y, float z, float w) {
    __half2 h0 = __floats2half2_rn(x, y), h1 = __floats2half2_rn(z, w);
    float2 o;
    o.x = *reinterpret_cast<float*>(&h0);
    o.y = *reinterpret_cast<float*>(&h1);
    return o;
}

// ---------------- graph preprocessing ----------------
__global__ void zero_cnt_k(int n) {
    int i = blockIdx.x * blockDim.x + threadIdx.x;
    if (i < n) g_cnt[i] = 0;
}

// 2 edges per thread, vectorized dst load
__global__ void hist_dst_k(const int* __restrict__ ei, int E) {
    int t = blockIdx.x * blockDim.x + threadIdx.x;
    int e = t * 2;
    if (e < E) {
        int2 d = *(const int2*)(ei + E + e);
        atomicAdd(&g_cnt[d.x], 1);
        atomicAdd(&g_cnt[d.y], 1);
    }
}

__global__ void scan_k(int n) {
    __shared__ int partial[1024];
    int tid = threadIdx.x;
    int chunk = (n + 1023) / 1024;
    int beg = tid * chunk;
    int end = min(beg + chunk, n);
    int s = 0;
    for (int i = beg; i < end; i++) s += g_cnt[i];
    partial[tid] = s;
    __syncthreads();
    for (int d = 1; d < 1024; d <<= 1) {
        int v = (tid >= d) ? partial[tid - d] : 0;
        __syncthreads();
        partial[tid] += v;
        __syncthreads();
    }
    int run = (tid == 0) ? 0 : partial[tid - 1];
    for (int i = beg; i < end; i++) {
        g_off[i] = run;
        g_cur[i] = run;
        int c = g_cnt[i];
        run += c;
        g_dis[i] = rsqrtf(1.0f + (float)c);
    }
    if (tid == 0) g_off[n] = partial[1023];
}

// 2 edges per thread, vectorized src+dst loads
__global__ void build_csr_k(const int* __restrict__ ei, int E) {
    int t = blockIdx.x * blockDim.x + threadIdx.x;
    int e = t * 2;
    if (e >= E) return;
    int2 s = *(const int2*)(ei + e);
    int2 d = *(const int2*)(ei + E + e);
    int p0 = atomicAdd(&g_cur[d.x], 1);
    g_csr[p0] = s.x;
    int p1 = atomicAdd(&g_cur[d.y], 1);
    g_csr[p1] = s.y;
}

// ---------------- TF32 tensor-core GEMM: g_h16[M,:] = dis[row] * (A @ W) ------
// A = fp32 input x (use_ga==0) or fp16 g_a16 (use_ga==1).
// block tile 128x128, 8 warps (4Mx2N), warp tile 32x64, K chunked by 32.
__global__ __launch_bounds__(256, 2)
void gemm_tf32_k(const float* __restrict__ Ax, const float* __restrict__ W,
                 int M, int use_ga)
{
    __shared__ unsigned As[128][36];
    __shared__ unsigned Bs[32][132];

    int tid  = threadIdx.x;
    int wid  = tid >> 5;
    int lane = tid & 31;
    int g    = lane >> 2;
    int tig  = lane & 3;
    int warp_m = wid & 3;
    int warp_n = wid >> 2;
    int row0 = blockIdx.x * 128;

    float acc[2][8][4];
#pragma unroll
    for (int mf = 0; mf < 2; mf++)
#pragma unroll
        for (int nf = 0; nf < 8; nf++)
#pragma unroll
            for (int i = 0; i < 4; i++) acc[mf][nf][i] = 0.f;

    for (int kb = 0; kb < 128; kb += 32) {
        if (use_ga) {
            const __half* A16 = g_a16;
#pragma unroll
            for (int l = 0; l < 2; l++) {
                int idx = tid + l * 256;          // 0..511
                int r  = idx >> 2;
                int c8 = idx & 3;
                int gr = row0 + r;
                if (gr > M - 1) gr = M - 1;
                float4 raw = *(const float4*)(A16 + (size_t)gr * 128 + kb + c8 * 8);
                float4 f0 = h8_to_f4(make_float2(raw.x, raw.y));
                float4 f1 = h8_to_f4(make_float2(raw.z, raw.w));
                unsigned* d = &As[r][c8 * 8];
                d[0] = f2tf32(f0.x); d[1] = f2tf32(f0.y);
                d[2] = f2tf32(f0.z); d[3] = f2tf32(f0.w);
                d[4] = f2tf32(f1.x); d[5] = f2tf32(f1.y);
                d[6] = f2tf32(f1.z); d[7] = f2tf32(f1.w);
            }
        } else {
#pragma unroll
            for (int l = 0; l < 4; l++) {
                int idx = tid + l * 256;
                int r  = idx >> 3;
                int c4 = idx & 7;
                int gr = row0 + r;
                if (gr > M - 1) gr = M - 1;
                float4 v = *(const float4*)(Ax + (size_t)gr * 128 + kb + c4 * 4);
                unsigned* d = &As[r][c4 * 4];
                d[0] = f2tf32(v.x); d[1] = f2tf32(v.y);
                d[2] = f2tf32(v.z); d[3] = f2tf32(v.w);
            }
        }
#pragma unroll
        for (int l = 0; l < 4; l++) {
            int idx = tid + l * 256;
            int r  = idx >> 5;
            int c4 = idx & 31;
            float4 v = *(const float4*)(W + (size_t)(kb + r) * 128 + c4 * 4);
            unsigned* d = &Bs[r][c4 * 4];
            d[0] = f2tf32(v.x); d[1] = f2tf32(v.y);
            d[2] = f2tf32(v.z); d[3] = f2tf32(v.w);
        }
        __syncthreads();

#pragma unroll
        for (int ks = 0; ks < 4; ks++) {
            int k0 = ks * 8;
            unsigned a[2][4];
#pragma unroll
            for (int mf = 0; mf < 2; mf++) {
                int rb = warp_m * 32 + mf * 16 + g;
                a[mf][0] = As[rb][k0 + tig];
                a[mf][1] = As[rb + 8][k0 + tig];
                a[mf][2] = As[rb][k0 + tig + 4];
                a[mf][3] = As[rb + 8][k0 + tig + 4];
            }
            unsigned b[8][2];
#pragma unroll
            for (int nf = 0; nf < 8; nf++) {
                int cb = warp_n * 64 + nf * 8 + g;
                b[nf][0] = Bs[k0 + tig][cb];
                b[nf][1] = Bs[k0 + tig + 4][cb];
            }
#pragma unroll
            for (int mf = 0; mf < 2; mf++)
#pragma unroll
                for (int nf = 0; nf < 8; nf++) {
                    asm volatile(
                        "mma.sync.aligned.m16n8k8.row.col.f32.tf32.tf32.f32 "
                        "{%0,%1,%2,%3}, {%4,%5,%6,%7}, {%8,%9}, {%0,%1,%2,%3};"
                        : "+f"(acc[mf][nf][0]), "+f"(acc[mf][nf][1]),
                          "+f"(acc[mf][nf][2]), "+f"(acc[mf][nf][3])
                        : "r"(a[mf][0]), "r"(a[mf][1]), "r"(a[mf][2]), "r"(a[mf][3]),
                          "r"(b[nf][0]), "r"(b[nf][1]));
                }
        }
        __syncthreads();
    }

    // epilogue: pre-scale each row by dis[row], write fp16
#pragma unroll
    for (int mf = 0; mf < 2; mf++) {
        int rb = row0 + warp_m * 32 + mf * 16 + g;
        float d0 = (rb < M)     ? g_dis[rb]     : 0.f;
        float d1 = (rb + 8 < M) ? g_dis[rb + 8] : 0.f;
#pragma unroll
        for (int nf = 0; nf < 8; nf++) {
            int col = warp_n * 64 + nf * 8 + tig * 2;
            if (rb < M) {
                __half2 v = __floats2half2_rn(d0 * acc[mf][nf][0], d0 * acc[mf][nf][1]);
                *(__half2*)(g_h16 + (size_t)rb * 128 + col) = v;
            }
            if (rb + 8 < M) {
                __half2 v = __floats2half2_rn(d1 * acc[mf][nf][2], d1 * acc[mf][nf][3]);
                *(__half2*)(g_h16 + (size_t)(rb + 8) * 128 + col) = v;
            }
        }
    }
}

// ---------------- aggregation: warp per node, pure gather+add ----------------
// g_h16 rows are pre-scaled (h' = dis[src]*h), so: out = dv*(sum_src h' + h'_self) + b
// writes g_a16 (relu); if W4 != null, writes g_t[w] = dv_implicit... g_t = dv * (relu_out . W4)
__global__ void agg128_k(const float* __restrict__ b, int M,
                         const float* __restrict__ W4)
{
    int w = (blockIdx.x * blockDim.x + threadIdx.x) >> 5;
    if (w >= M) return;
    int lane = threadIdx.x & 31;
    const __half* __restrict__ h = g_h16;
    int beg = g_off[w], end = g_off[w + 1];
    float dv = g_dis[w];

    float ax = 0.f, ay = 0.f, az = 0.f, aw = 0.f;
    int e = beg;
    // peel to 4-alignment so int4 index loads are legal
    for (; e < end && (e & 3); e++) {
        int s0 = g_csr[e];
        float4 h0 = h8_to_f4(((const float2*)(h + (size_t)s0 * 128))[lane]);
        ax += h0.x; ay += h0.y; az += h0.z; aw += h0.w;
    }
    for (; e + 8 <= end; e += 8) {
        int4 i0 = *(const int4*)(g_csr + e);
        int4 i1 = *(const int4*)(g_csr + e + 4);
        float2 r0 = ((const float2*)(h + (size_t)i0.x * 128))[lane];
        float2 r1 = ((const float2*)(h + (size_t)i0.y * 128))[lane];
        float2 r2 = ((const float2*)(h + (size_t)i0.z * 128))[lane];
        float2 r3 = ((const float2*)(h + (size_t)i0.w * 128))[lane];
        float2 r4 = ((const float2*)(h + (size_t)i1.x * 128))[lane];
        float2 r5 = ((const float2*)(h + (size_t)i1.y * 128))[lane];
        float2 r6 = ((const float2*)(h + (size_t)i1.z * 128))[lane];
        float2 r7 = ((const float2*)(h + (size_t)i1.w * 128))[lane];
        float4 h0 = h8_to_f4(r0), h1 = h8_to_f4(r1);
        float4 h2 = h8_to_f4(r2), h3 = h8_to_f4(r3);
        float4 h4 = h8_to_f4(r4), h5 = h8_to_f4(r5);
        float4 h6 = h8_to_f4(r6), h7 = h8_to_f4(r7);
        ax += (h0.x + h1.x) + (h2.x + h3.x) + (h4.x + h5.x) + (h6.x + h7.x);
        ay += (h0.y + h1.y) + (h2.y + h3.y) + (h4.y + h5.y) + (h6.y + h7.y);
        az += (h0.z + h1.z) + (h2.z + h3.z) + (h4.z + h5.z) + (h6.z + h7.z);
        aw += (h0.w + h1.w) + (h2.w + h3.w) + (h4.w + h5.w) + (h6.w + h7.w);
    }
    for (; e < end; e++) {
        int s0 = g_csr[e];
        float4 h0 = h8_to_f4(((const float2*)(h + (size_t)s0 * 128))[lane]);
        ax += h0.x; ay += h0.y; az += h0.z; aw += h0.w;
    }

    // self term: h' already contains dis[w]*h
    float4 hs = h8_to_f4(((const float2*)(h + (size_t)w * 128))[lane]);
    float4 bb = ((const float4*)b)[lane];
    float rx = fmaxf(dv * (ax + hs.x) + bb.x, 0.f);
    float ry = fmaxf(dv * (ay + hs.y) + bb.y, 0.f);
    float rz = fmaxf(dv * (az + hs.z) + bb.z, 0.f);
    float rw = fmaxf(dv * (aw + hs.w) + bb.w, 0.f);

    if (W4 == nullptr) {
        ((float2*)(g_a16 + (size_t)w * 128))[lane] = f4_to_h8(rx, ry, rz, rw);
    } else {
        float4 wv = ((const float4*)W4)[lane];
        float s = rx * wv.x + ry * wv.y + rz * wv.z + rw * wv.w;
#pragma unroll
        for (int o = 16; o; o >>= 1) s += __shfl_xor_sync(0xFFFFFFFFu, s, o);
        if (lane == 0) g_t[w] = dv * s;   // pre-scaled scalar t' = dis * t
    }
}

// g_t is pre-scaled: out[v] = dv * (sum_src t'[src] + t'[v]) + b4
__global__ void final_agg_k(const float* __restrict__ b4, float* __restrict__ out, int M)
{
    int v = blockIdx.x * blockDim.x + threadIdx.x;
    if (v >= M) return;
    float dv = g_dis[v];
    int beg = g_off[v], end = g_off[v + 1];
    float s = 0.f;
    int e = beg;
    for (; e < end && (e & 3); e++) s += g_t[g_csr[e]];
    for (; e + 4 <= end; e += 4) {
        int4 i0 = *(const int4*)(g_csr + e);
        s += g_t[i0.x] + g_t[i0.y] + g_t[i0.z] + g_t[i0.w];
    }
    for (; e < end; e++) s += g_t[g_csr[e]];
    out[v] = dv * (s + g_t[v]) + b4[0];
}

// ---------------- launch ----------------
extern "C" void kernel_launch(void* const* d_in, const int* in_sizes, int n_in,
                              void* d_out, int out_size)
{
    const float* x  = (const float*)d_in[0];
    const int*   ei = (const int*)d_in[1];      // int32 on the wire
    const float* W1 = (const float*)d_in[2]; const float* b1 = (const float*)d_in[3];
    const float* W2 = (const float*)d_in[4]; const float* b2 = (const float*)d_in[5];
    const float* W3 = (const float*)d_in[6]; const float* b3 = (const float*)d_in[7];
    const float* W4 = (const float*)d_in[8]; const float* b4 = (const float*)d_in[9];

    int N = in_sizes[0] / 128;   // 50000
    int E = in_sizes[1] / 2;     // 1600000
    float* out = (float*)d_out;

    // graph preprocessing
    zero_cnt_k <<<(N + 255) / 256, 256>>>(N);
    hist_dst_k <<<(E / 2 + 255) / 256, 256>>>(ei, E);
    scan_k     <<<1, 1024>>>(N);
    build_csr_k<<<(E / 2 + 255) / 256, 256>>>(ei, E);

    int gemm_blocks = (N + 127) / 128;
    int agg_blocks  = (N * 32 + 255) / 256;

    gemm_tf32_k<<<gemm_blocks, 256>>>(x, W1, N, 0);
    agg128_k   <<<agg_blocks, 256>>>(b1, N, nullptr);

    gemm_tf32_k<<<gemm_blocks, 256>>>(x, W2, N, 1);
    agg128_k   <<<agg_blocks, 256>>>(b2, N, nullptr);

    gemm_tf32_k<<<gemm_blocks, 256>>>(x, W3, N, 1);
    agg128_k   <<<agg_blocks, 256>>>(b3, N, W4);   // fused relu + dot(W4) -> g_t (pre-scaled)

    final_agg_k<<<(N + 255) / 256, 256>>>(b4, out, N);
}

// round 7
// speedup vs baseline: 2.3990x; 1.4560x over previous
#include <cuda_runtime.h>
#include <cuda_fp16.h>
#include <cstddef>

#define NN_MAX 50000
#define EE_MAX 1600000
#define SCAN_B 1024
#define NB_MAX 64

// -------- scratch (device globals; no allocation allowed) --------
__device__ __align__(16) float  g_dis[NN_MAX];      // 1/sqrt(1+in_deg)
__device__ int    g_cnt[NN_MAX];
__device__ int    g_cur[NN_MAX];
__device__ int    g_off[NN_MAX + 1];
__device__ int    g_sl[NN_MAX];                     // block-local exclusive scan
__device__ int    g_bsum[NB_MAX];                   // per-block totals
__device__ int    g_boff[NB_MAX];                   // scanned block offsets
__device__ __align__(16) int g_csr[EE_MAX];
__device__ __align__(16) __half g_h16[(size_t)NN_MAX * 128];  // post-GEMM, PRE-SCALED by dis[row]
__device__ __align__(16) __half g_a16[(size_t)NN_MAX * 128];  // post-agg activations
__device__ float  g_t[NN_MAX];                      // final scalar projection, PRE-SCALED

// ---------------- helpers ----------------
__device__ __forceinline__ unsigned f2tf32(float f) {
    unsigned u;
    asm("cvt.rna.tf32.f32 %0, %1;" : "=r"(u) : "f"(f));
    return u;
}
__device__ __forceinline__ float4 h8_to_f4(float2 raw) {
    __half2 ha = *reinterpret_cast<__half2*>(&raw.x);
    __half2 hb = *reinterpret_cast<__half2*>(&raw.y);
    float2 fa = __half22float2(ha), fb = __half22float2(hb);
    return make_float4(fa.x, fa.y, fb.x, fb.y);
}
__device__ __forceinline__ float2 f4_to_h8(float x, float y, float z, float w) {
    __half2 h0 = __floats2half2_rn(x, y), h1 = __floats2half2_rn(z, w);
    float2 o;
    o.x = *reinterpret_cast<float*>(&h0);
    o.y = *reinterpret_cast<float*>(&h1);
    return o;
}
// fp16 pair-sum of two packed rows, then widen to f32x4
__device__ __forceinline__ float4 pairsum_f4(float2 ra, float2 rb) {
    __half2 alo = *reinterpret_cast<__half2*>(&ra.x);
    __half2 ahi = *reinterpret_cast<__half2*>(&ra.y);
    __half2 blo = *reinterpret_cast<__half2*>(&rb.x);
    __half2 bhi = *reinterpret_cast<__half2*>(&rb.y);
    __half2 slo = __hadd2(alo, blo);
    __half2 shi = __hadd2(ahi, bhi);
    float2 fa = __half22float2(slo), fb = __half22float2(shi);
    return make_float4(fa.x, fa.y, fb.x, fb.y);
}

// ---------------- graph preprocessing ----------------
__global__ void zero_cnt_k(int n) {
    int i = blockIdx.x * blockDim.x + threadIdx.x;
    if (i < n) g_cnt[i] = 0;
}

// 4 edges per thread, int4 dst loads, 4 independent atomic chains
__global__ void hist_dst_k(const int* __restrict__ ei, int E) {
    int t = blockIdx.x * blockDim.x + threadIdx.x;
    int e = t * 4;
    if (e + 3 < E) {
        int4 d = *(const int4*)(ei + E + e);
        atomicAdd(&g_cnt[d.x], 1);
        atomicAdd(&g_cnt[d.y], 1);
        atomicAdd(&g_cnt[d.z], 1);
        atomicAdd(&g_cnt[d.w], 1);
    } else {
        for (; e < E; e++) atomicAdd(&g_cnt[ei[E + e]], 1);
    }
}

// two-level scan: s1 block-local, s2 block totals, s3 combine + dis
__global__ void scan1_k(int n) {
    __shared__ int sh[SCAN_B];
    int t = threadIdx.x;
    int i = blockIdx.x * SCAN_B + t;
    int v = (i < n) ? g_cnt[i] : 0;
    sh[t] = v;
    __syncthreads();
    for (int d = 1; d < SCAN_B; d <<= 1) {
        int u = (t >= d) ? sh[t - d] : 0;
        __syncthreads();
        sh[t] += u;
        __syncthreads();
    }
    if (i < n) g_sl[i] = sh[t] - v;            // exclusive
    if (t == SCAN_B - 1) g_bsum[blockIdx.x] = sh[t];
}

__global__ void scan2_k(int nb) {
    __shared__ int sh[NB_MAX];
    int t = threadIdx.x;
    int v = (t < nb) ? g_bsum[t] : 0;
    sh[t] = v;
    __syncthreads();
    for (int d = 1; d < NB_MAX; d <<= 1) {
        int u = (t >= d) ? sh[t - d] : 0;
        __syncthreads();
        sh[t] += u;
        __syncthreads();
    }
    if (t < nb) g_boff[t] = sh[t] - v;         // exclusive
}

__global__ void scan3_k(int n) {
    int i = blockIdx.x * blockDim.x + threadIdx.x;
    if (i >= n) return;
    int off = g_sl[i] + g_boff[i >> 10];
    g_off[i] = off;
    g_cur[i] = off;
    int c = g_cnt[i];
    g_dis[i] = rsqrtf(1.0f + (float)c);
    if (i == n - 1) g_off[n] = off + c;
}

// 4 edges per thread, int4 loads, 4 independent atomic+store chains
__global__ void build_csr_k(const int* __restrict__ ei, int E) {
    int t = blockIdx.x * blockDim.x + threadIdx.x;
    int e = t * 4;
    if (e + 3 < E) {
        int4 s = *(const int4*)(ei + e);
        int4 d = *(const int4*)(ei + E + e);
        int p0 = atomicAdd(&g_cur[d.x], 1);
        int p1 = atomicAdd(&g_cur[d.y], 1);
        int p2 = atomicAdd(&g_cur[d.z], 1);
        int p3 = atomicAdd(&g_cur[d.w], 1);
        g_csr[p0] = s.x;
        g_csr[p1] = s.y;
        g_csr[p2] = s.z;
        g_csr[p3] = s.w;
    } else {
        for (; e < E; e++) {
            int p = atomicAdd(&g_cur[ei[E + e]], 1);
            g_csr[p] = ei[e];
        }
    }
}

// ---------------- TF32 tensor-core GEMM: g_h16[M,:] = dis[row] * (A @ W) ------
__global__ __launch_bounds__(256, 2)
void gemm_tf32_k(const float* __restrict__ Ax, const float* __restrict__ W,
                 int M, int use_ga)
{
    __shared__ unsigned As[128][36];
    __shared__ unsigned Bs[32][132];

    int tid  = threadIdx.x;
    int wid  = tid >> 5;
    int lane = tid & 31;
    int g    = lane >> 2;
    int tig  = lane & 3;
    int warp_m = wid & 3;
    int warp_n = wid >> 2;
    int row0 = blockIdx.x * 128;

    float acc[2][8][4];
#pragma unroll
    for (int mf = 0; mf < 2; mf++)
#pragma unroll
        for (int nf = 0; nf < 8; nf++)
#pragma unroll
            for (int i = 0; i < 4; i++) acc[mf][nf][i] = 0.f;

    for (int kb = 0; kb < 128; kb += 32) {
        if (use_ga) {
            const __half* A16 = g_a16;
#pragma unroll
            for (int l = 0; l < 2; l++) {
                int idx = tid + l * 256;
                int r  = idx >> 2;
                int c8 = idx & 3;
                int gr = row0 + r;
                if (gr > M - 1) gr = M - 1;
                float4 raw = *(const float4*)(A16 + (size_t)gr * 128 + kb + c8 * 8);
                float4 f0 = h8_to_f4(make_float2(raw.x, raw.y));
                float4 f1 = h8_to_f4(make_float2(raw.z, raw.w));
                unsigned* d = &As[r][c8 * 8];
                d[0] = f2tf32(f0.x); d[1] = f2tf32(f0.y);
                d[2] = f2tf32(f0.z); d[3] = f2tf32(f0.w);
                d[4] = f2tf32(f1.x); d[5] = f2tf32(f1.y);
                d[6] = f2tf32(f1.z); d[7] = f2tf32(f1.w);
            }
        } else {
#pragma unroll
            for (int l = 0; l < 4; l++) {
                int idx = tid + l * 256;
                int r  = idx >> 3;
                int c4 = idx & 7;
                int gr = row0 + r;
                if (gr > M - 1) gr = M - 1;
                float4 v = *(const float4*)(Ax + (size_t)gr * 128 + kb + c4 * 4);
                unsigned* d = &As[r][c4 * 4];
                d[0] = f2tf32(v.x); d[1] = f2tf32(v.y);
                d[2] = f2tf32(v.z); d[3] = f2tf32(v.w);
            }
        }
#pragma unroll
        for (int l = 0; l < 4; l++) {
            int idx = tid + l * 256;
            int r  = idx >> 5;
            int c4 = idx & 31;
            float4 v = *(const float4*)(W + (size_t)(kb + r) * 128 + c4 * 4);
            unsigned* d = &Bs[r][c4 * 4];
            d[0] = f2tf32(v.x); d[1] = f2tf32(v.y);
            d[2] = f2tf32(v.z); d[3] = f2tf32(v.w);
        }
        __syncthreads();

#pragma unroll
        for (int ks = 0; ks < 4; ks++) {
            int k0 = ks * 8;
            unsigned a[2][4];
#pragma unroll
            for (int mf = 0; mf < 2; mf++) {
                int rb = warp_m * 32 + mf * 16 + g;
                a[mf][0] = As[rb][k0 + tig];
                a[mf][1] = As[rb + 8][k0 + tig];
                a[mf][2] = As[rb][k0 + tig + 4];
                a[mf][3] = As[rb + 8][k0 + tig + 4];
            }
            unsigned b[8][2];
#pragma unroll
            for (int nf = 0; nf < 8; nf++) {
                int cb = warp_n * 64 + nf * 8 + g;
                b[nf][0] = Bs[k0 + tig][cb];
                b[nf][1] = Bs[k0 + tig + 4][cb];
            }
#pragma unroll
            for (int mf = 0; mf < 2; mf++)
#pragma unroll
                for (int nf = 0; nf < 8; nf++) {
                    asm volatile(
                        "mma.sync.aligned.m16n8k8.row.col.f32.tf32.tf32.f32 "
                        "{%0,%1,%2,%3}, {%4,%5,%6,%7}, {%8,%9}, {%0,%1,%2,%3};"
                        : "+f"(acc[mf][nf][0]), "+f"(acc[mf][nf][1]),
                          "+f"(acc[mf][nf][2]), "+f"(acc[mf][nf][3])
                        : "r"(a[mf][0]), "r"(a[mf][1]), "r"(a[mf][2]), "r"(a[mf][3]),
                          "r"(b[nf][0]), "r"(b[nf][1]));
                }
        }
        __syncthreads();
    }

#pragma unroll
    for (int mf = 0; mf < 2; mf++) {
        int rb = row0 + warp_m * 32 + mf * 16 + g;
        float d0 = (rb < M)     ? g_dis[rb]     : 0.f;
        float d1 = (rb + 8 < M) ? g_dis[rb + 8] : 0.f;
#pragma unroll
        for (int nf = 0; nf < 8; nf++) {
            int col = warp_n * 64 + nf * 8 + tig * 2;
            if (rb < M) {
                __half2 v = __floats2half2_rn(d0 * acc[mf][nf][0], d0 * acc[mf][nf][1]);
                *(__half2*)(g_h16 + (size_t)rb * 128 + col) = v;
            }
            if (rb + 8 < M) {
                __half2 v = __floats2half2_rn(d1 * acc[mf][nf][2], d1 * acc[mf][nf][3]);
                *(__half2*)(g_h16 + (size_t)(rb + 8) * 128 + col) = v;
            }
        }
    }
}

// ---------------- aggregation: warp per node, pure gather+add ----------------
__global__ void agg128_k(const float* __restrict__ b, int M,
                         const float* __restrict__ W4)
{
    int w = (blockIdx.x * blockDim.x + threadIdx.x) >> 5;
    if (w >= M) return;
    int lane = threadIdx.x & 31;
    const __half* __restrict__ h = g_h16;
    int beg = g_off[w], end = g_off[w + 1];
    float dv = g_dis[w];

    float ax = 0.f, ay = 0.f, az = 0.f, aw = 0.f;
    int e = beg;
    for (; e < end && (e & 3); e++) {
        int s0 = g_csr[e];
        float4 h0 = h8_to_f4(((const float2*)(h + (size_t)s0 * 128))[lane]);
        ax += h0.x; ay += h0.y; az += h0.z; aw += h0.w;
    }
    for (; e + 8 <= end; e += 8) {
        int4 i0 = *(const int4*)(g_csr + e);
        int4 i1 = *(const int4*)(g_csr + e + 4);
        float2 r0 = ((const float2*)(h + (size_t)i0.x * 128))[lane];
        float2 r1 = ((const float2*)(h + (size_t)i0.y * 128))[lane];
        float2 r2 = ((const float2*)(h + (size_t)i0.z * 128))[lane];
        float2 r3 = ((const float2*)(h + (size_t)i0.w * 128))[lane];
        float2 r4 = ((const float2*)(h + (size_t)i1.x * 128))[lane];
        float2 r5 = ((const float2*)(h + (size_t)i1.y * 128))[lane];
        float2 r6 = ((const float2*)(h + (size_t)i1.z * 128))[lane];
        float2 r7 = ((const float2*)(h + (size_t)i1.w * 128))[lane];
        // one-level fp16 pair-sum, then fp32 accumulate
        float4 p0 = pairsum_f4(r0, r1);
        float4 p1 = pairsum_f4(r2, r3);
        float4 p2 = pairsum_f4(r4, r5);
        float4 p3 = pairsum_f4(r6, r7);
        ax += (p0.x + p1.x) + (p2.x + p3.x);
        ay += (p0.y + p1.y) + (p2.y + p3.y);
        az += (p0.z + p1.z) + (p2.z + p3.z);
        aw += (p0.w + p1.w) + (p2.w + p3.w);
    }
    for (; e < end; e++) {
        int s0 = g_csr[e];
        float4 h0 = h8_to_f4(((const float2*)(h + (size_t)s0 * 128))[lane]);
        ax += h0.x; ay += h0.y; az += h0.z; aw += h0.w;
    }

    float4 hs = h8_to_f4(((const float2*)(h + (size_t)w * 128))[lane]);
    float4 bb = ((const float4*)b)[lane];
    float rx = fmaxf(dv * (ax + hs.x) + bb.x, 0.f);
    float ry = fmaxf(dv * (ay + hs.y) + bb.y, 0.f);
    float rz = fmaxf(dv * (az + hs.z) + bb.z, 0.f);
    float rw = fmaxf(dv * (aw + hs.w) + bb.w, 0.f);

    if (W4 == nullptr) {
        ((float2*)(g_a16 + (size_t)w * 128))[lane] = f4_to_h8(rx, ry, rz, rw);
    } else {
        float4 wv = ((const float4*)W4)[lane];
        float s = rx * wv.x + ry * wv.y + rz * wv.z + rw * wv.w;
#pragma unroll
        for (int o = 16; o; o >>= 1) s += __shfl_xor_sync(0xFFFFFFFFu, s, o);
        if (lane == 0) g_t[w] = dv * s;
    }
}

__global__ void final_agg_k(const float* __restrict__ b4, float* __restrict__ out, int M)
{
    int v = blockIdx.x * blockDim.x + threadIdx.x;
    if (v >= M) return;
    float dv = g_dis[v];
    int beg = g_off[v], end = g_off[v + 1];
    float s = 0.f;
    int e = beg;
    for (; e < end && (e & 3); e++) s += g_t[g_csr[e]];
    for (; e + 4 <= end; e += 4) {
        int4 i0 = *(const int4*)(g_csr + e);
        s += g_t[i0.x] + g_t[i0.y] + g_t[i0.z] + g_t[i0.w];
    }
    for (; e < end; e++) s += g_t[g_csr[e]];
    out[v] = dv * (s + g_t[v]) + b4[0];
}

// ---------------- launch ----------------
extern "C" void kernel_launch(void* const* d_in, const int* in_sizes, int n_in,
                              void* d_out, int out_size)
{
    const float* x  = (const float*)d_in[0];
    const int*   ei = (const int*)d_in[1];
    const float* W1 = (const float*)d_in[2]; const float* b1 = (const float*)d_in[3];
    const float* W2 = (const float*)d_in[4]; const float* b2 = (const float*)d_in[5];
    const float* W3 = (const float*)d_in[6]; const float* b3 = (const float*)d_in[7];
    const float* W4 = (const float*)d_in[8]; const float* b4 = (const float*)d_in[9];

    int N = in_sizes[0] / 128;   // 50000
    int E = in_sizes[1] / 2;     // 1600000
    float* out = (float*)d_out;

    int nb = (N + SCAN_B - 1) / SCAN_B;      // 49

    // graph preprocessing
    zero_cnt_k <<<(N + 255) / 256, 256>>>(N);
    hist_dst_k <<<(E / 4 + 255) / 256, 256>>>(ei, E);
    scan1_k    <<<nb, SCAN_B>>>(N);
    scan2_k    <<<1, NB_MAX>>>(nb);
    scan3_k    <<<(N + 255) / 256, 256>>>(N);
    build_csr_k<<<(E / 4 + 255) / 256, 256>>>(ei, E);

    int gemm_blocks = (N + 127) / 128;
    int agg_blocks  = (N * 32 + 255) / 256;

    gemm_tf32_k<<<gemm_blocks, 256>>>(x, W1, N, 0);
    agg128_k   <<<agg_blocks, 256>>>(b1, N, nullptr);

    gemm_tf32_k<<<gemm_blocks, 256>>>(x, W2, N, 1);
    agg128_k   <<<agg_blocks, 256>>>(b2, N, nullptr);

    gemm_tf32_k<<<gemm_blocks, 256>>>(x, W3, N, 1);
    agg128_k   <<<agg_blocks, 256>>>(b3, N, W4);

    final_agg_k<<<(N + 255) / 256, 256>>>(b4, out, N);
}

// round 8
// speedup vs baseline: 2.6277x; 1.0953x over previous
#include <cuda_runtime.h>
#include <cuda_fp16.h>
#include <cstddef>

#define NN_MAX 50000
#define EE_MAX 1600000
#define SCAN_B 1024
#define NB_MAX 64

// -------- scratch (device globals; no allocation allowed) --------
__device__ __align__(16) float  g_dis[NN_MAX];      // 1/sqrt(1+in_deg)
__device__ int    g_cnt[NN_MAX];
__device__ int    g_cur[NN_MAX];
__device__ int    g_off[NN_MAX + 1];
__device__ int    g_sl[NN_MAX];                     // block-local exclusive scan
__device__ int    g_bsum[NB_MAX];                   // per-block totals
__device__ __align__(16) int g_csr[EE_MAX];
__device__ __align__(16) __half g_h16[(size_t)NN_MAX * 128];  // post-GEMM, PRE-SCALED by dis[row]
__device__ __align__(16) __half g_a16[(size_t)NN_MAX * 128];  // post-agg activations
__device__ float  g_t[NN_MAX];                      // final scalar projection, PRE-SCALED

// ---------------- helpers ----------------
__device__ __forceinline__ float4 h8_to_f4(float2 raw) {
    __half2 ha = *reinterpret_cast<__half2*>(&raw.x);
    __half2 hb = *reinterpret_cast<__half2*>(&raw.y);
    float2 fa = __half22float2(ha), fb = __half22float2(hb);
    return make_float4(fa.x, fa.y, fb.x, fb.y);
}
__device__ __forceinline__ float2 f4_to_h8(float x, float y, float z, float w) {
    __half2 h0 = __floats2half2_rn(x, y), h1 = __floats2half2_rn(z, w);
    float2 o;
    o.x = *reinterpret_cast<float*>(&h0);
    o.y = *reinterpret_cast<float*>(&h1);
    return o;
}
// fp16 pair-sum of two packed rows, then widen to f32x4
__device__ __forceinline__ float4 pairsum_f4(float2 ra, float2 rb) {
    __half2 alo = *reinterpret_cast<__half2*>(&ra.x);
    __half2 ahi = *reinterpret_cast<__half2*>(&ra.y);
    __half2 blo = *reinterpret_cast<__half2*>(&rb.x);
    __half2 bhi = *reinterpret_cast<__half2*>(&rb.y);
    __half2 slo = __hadd2(alo, blo);
    __half2 shi = __hadd2(ahi, bhi);
    float2 fa = __half22float2(slo), fb = __half22float2(shi);
    return make_float4(fa.x, fa.y, fb.x, fb.y);
}

// ---------------- graph preprocessing ----------------
__global__ void zero_cnt_k(int n) {
    int i = blockIdx.x * blockDim.x + threadIdx.x;
    if (i < n) g_cnt[i] = 0;
}

// 4 edges per thread, int4 dst loads
__global__ void hist_dst_k(const int* __restrict__ ei, int E) {
    int t = blockIdx.x * blockDim.x + threadIdx.x;
    int e = t * 4;
    if (e + 3 < E) {
        int4 d = *(const int4*)(ei + E + e);
        atomicAdd(&g_cnt[d.x], 1);
        atomicAdd(&g_cnt[d.y], 1);
        atomicAdd(&g_cnt[d.z], 1);
        atomicAdd(&g_cnt[d.w], 1);
    } else {
        for (; e < E; e++) atomicAdd(&g_cnt[ei[E + e]], 1);
    }
}

// block-local scan + per-block totals
__global__ void scan1_k(int n) {
    __shared__ int sh[SCAN_B];
    int t = threadIdx.x;
    int i = blockIdx.x * SCAN_B + t;
    int v = (i < n) ? g_cnt[i] : 0;
    sh[t] = v;
    __syncthreads();
    for (int d = 1; d < SCAN_B; d <<= 1) {
        int u = (t >= d) ? sh[t - d] : 0;
        __syncthreads();
        sh[t] += u;
        __syncthreads();
    }
    if (i < n) g_sl[i] = sh[t] - v;            // exclusive
    if (t == SCAN_B - 1) g_bsum[blockIdx.x] = sh[t];
}

// combine: every block redundantly scans the (<=64) block totals in smem
__global__ void scan3_k(int n, int nb) {
    __shared__ int sh[NB_MAX];
    int t = threadIdx.x;
    if (t < NB_MAX) sh[t] = (t < nb) ? g_bsum[t] : 0;
    __syncthreads();
    for (int d = 1; d < NB_MAX; d <<= 1) {
        int u = (t < NB_MAX && t >= d) ? sh[t - d] : 0;
        __syncthreads();
        if (t < NB_MAX) sh[t] += u;
        __syncthreads();
    }
    int i = blockIdx.x * blockDim.x + t;
    if (i >= n) return;
    int bidx = i >> 10;
    int boff = (bidx > 0) ? sh[bidx - 1] : 0;
    int off = g_sl[i] + boff;
    g_off[i] = off;
    g_cur[i] = off;
    int c = g_cnt[i];
    g_dis[i] = rsqrtf(1.0f + (float)c);
    if (i == n - 1) g_off[n] = off + c;
}

// 4 edges per thread, int4 loads
__global__ void build_csr_k(const int* __restrict__ ei, int E) {
    int t = blockIdx.x * blockDim.x + threadIdx.x;
    int e = t * 4;
    if (e + 3 < E) {
        int4 s = *(const int4*)(ei + e);
        int4 d = *(const int4*)(ei + E + e);
        int p0 = atomicAdd(&g_cur[d.x], 1);
        int p1 = atomicAdd(&g_cur[d.y], 1);
        int p2 = atomicAdd(&g_cur[d.z], 1);
        int p3 = atomicAdd(&g_cur[d.w], 1);
        g_csr[p0] = s.x;
        g_csr[p1] = s.y;
        g_csr[p2] = s.z;
        g_csr[p3] = s.w;
    } else {
        for (; e < E; e++) {
            int p = atomicAdd(&g_cur[ei[E + e]], 1);
            g_csr[p] = ei[e];
        }
    }
}

// ---------------- fp16 tensor-core GEMM: g_h16[M,:] = dis[row] * (A @ W) ------
// A = fp32 input x (use_ga==0) or fp16 g_a16 (use_ga==1); W fp32 -> fp16.
// block tile 128x128, 8 warps (4Mx2N), warp tile 32x64; mma.m16n8k16, K chunk 32.
// As2: half2 [128][20] (row stride 20 -> g*20 mod 32 conflict-free)
// Bs2: half2 [16][136], Bs2[k/2][n] = (W[2k'],W[2k'+1]) pairs (tig*8+g conflict-free)
__global__ __launch_bounds__(256, 2)
void gemm_fp16_k(const float* __restrict__ Ax, const float* __restrict__ W,
                 int M, int use_ga)
{
    __shared__ __align__(16) __half2 As2[128][20];
    __shared__ __align__(16) __half2 Bs2[16][136];

    int tid  = threadIdx.x;
    int wid  = tid >> 5;
    int lane = tid & 31;
    int g    = lane >> 2;
    int tig  = lane & 3;
    int warp_m = wid & 3;
    int warp_n = wid >> 2;
    int row0 = blockIdx.x * 128;

    float acc[2][8][4];
#pragma unroll
    for (int mf = 0; mf < 2; mf++)
#pragma unroll
        for (int nf = 0; nf < 8; nf++)
#pragma unroll
            for (int i = 0; i < 4; i++) acc[mf][nf][i] = 0.f;

    for (int kb = 0; kb < 128; kb += 32) {
        if (use_ga) {
            // fp16 A: pure copy, 128 rows x 16 half2 = 512 uint4 tasks
            const __half* A16 = g_a16;
#pragma unroll
            for (int l = 0; l < 2; l++) {
                int idx = tid + l * 256;          // 0..511
                int r  = idx >> 2;
                int c8 = idx & 3;                 // 8-half group
                int gr = row0 + r;
                if (gr > M - 1) gr = M - 1;
                float4 raw = *(const float4*)(A16 + (size_t)gr * 128 + kb + c8 * 8);
                *(float4*)(&As2[r][c8 * 4]) = raw;
            }
        } else {
            // fp32 A: 128 rows x 8 float4 = 1024 tasks, convert to half2
#pragma unroll
            for (int l = 0; l < 4; l++) {
                int idx = tid + l * 256;
                int r  = idx >> 3;
                int c4 = idx & 7;
                int gr = row0 + r;
                if (gr > M - 1) gr = M - 1;
                float4 v = *(const float4*)(Ax + (size_t)gr * 128 + kb + c4 * 4);
                As2[r][c4 * 2]     = __floats2half2_rn(v.x, v.y);
                As2[r][c4 * 2 + 1] = __floats2half2_rn(v.z, v.w);
            }
        }
        // W chunk: 16 k-pairs x 128 cols; thread handles 4 cols of one pair
#pragma unroll
        for (int l = 0; l < 2; l++) {
            int idx = tid + l * 256;              // 0..511
            int r  = idx >> 5;                    // k-pair 0..15
            int c4 = idx & 31;                    // col group of 4
            const float* w0 = W + (size_t)(kb + 2 * r) * 128 + c4 * 4;
            float4 v0 = *(const float4*)w0;
            float4 v1 = *(const float4*)(w0 + 128);
            __half2 p0 = __floats2half2_rn(v0.x, v1.x);
            __half2 p1 = __floats2half2_rn(v0.y, v1.y);
            __half2 p2 = __floats2half2_rn(v0.z, v1.z);
            __half2 p3 = __floats2half2_rn(v0.w, v1.w);
            __half2* d = &Bs2[r][c4 * 4];
            d[0] = p0; d[1] = p1; d[2] = p2; d[3] = p3;
        }
        __syncthreads();

#pragma unroll
        for (int ks = 0; ks < 2; ks++) {          // two k16 steps per chunk
            int k0 = ks * 8;                      // in half2 units
            unsigned a[2][4];
#pragma unroll
            for (int mf = 0; mf < 2; mf++) {
                int rb = warp_m * 32 + mf * 16 + g;
                a[mf][0] = *(unsigned*)&As2[rb][k0 + tig];
                a[mf][1] = *(unsigned*)&As2[rb + 8][k0 + tig];
                a[mf][2] = *(unsigned*)&As2[rb][k0 + tig + 4];
                a[mf][3] = *(unsigned*)&As2[rb + 8][k0 + tig + 4];
            }
            unsigned b[8][2];
#pragma unroll
            for (int nf = 0; nf < 8; nf++) {
                int cb = warp_n * 64 + nf * 8 + g;
                b[nf][0] = *(unsigned*)&Bs2[k0 + tig][cb];
                b[nf][1] = *(unsigned*)&Bs2[k0 + tig + 4][cb];
            }
#pragma unroll
            for (int mf = 0; mf < 2; mf++)
#pragma unroll
                for (int nf = 0; nf < 8; nf++) {
                    asm volatile(
                        "mma.sync.aligned.m16n8k16.row.col.f32.f16.f16.f32 "
                        "{%0,%1,%2,%3}, {%4,%5,%6,%7}, {%8,%9}, {%0,%1,%2,%3};"
                        : "+f"(acc[mf][nf][0]), "+f"(acc[mf][nf][1]),
                          "+f"(acc[mf][nf][2]), "+f"(acc[mf][nf][3])
                        : "r"(a[mf][0]), "r"(a[mf][1]), "r"(a[mf][2]), "r"(a[mf][3]),
                          "r"(b[nf][0]), "r"(b[nf][1]));
                }
        }
        __syncthreads();
    }

    // epilogue: pre-scale each row by dis[row], write fp16
#pragma unroll
    for (int mf = 0; mf < 2; mf++) {
        int rb = row0 + warp_m * 32 + mf * 16 + g;
        float d0 = (rb < M)     ? g_dis[rb]     : 0.f;
        float d1 = (rb + 8 < M) ? g_dis[rb + 8] : 0.f;
#pragma unroll
        for (int nf = 0; nf < 8; nf++) {
            int col = warp_n * 64 + nf * 8 + tig * 2;
            if (rb < M) {
                __half2 v = __floats2half2_rn(d0 * acc[mf][nf][0], d0 * acc[mf][nf][1]);
                *(__half2*)(g_h16 + (size_t)rb * 128 + col) = v;
            }
            if (rb + 8 < M) {
                __half2 v = __floats2half2_rn(d1 * acc[mf][nf][2], d1 * acc[mf][nf][3]);
                *(__half2*)(g_h16 + (size_t)(rb + 8) * 128 + col) = v;
            }
        }
    }
}

// ---------------- aggregation: warp per node, pure gather+add ----------------
__global__ void agg128_k(const float* __restrict__ b, int M,
                         const float* __restrict__ W4)
{
    int w = (blockIdx.x * blockDim.x + threadIdx.x) >> 5;
    if (w >= M) return;
    int lane = threadIdx.x & 31;
    const __half* __restrict__ h = g_h16;
    int beg = g_off[w], end = g_off[w + 1];
    float dv = g_dis[w];

    float ax = 0.f, ay = 0.f, az = 0.f, aw = 0.f;
    int e = beg;
    for (; e < end && (e & 3); e++) {
        int s0 = g_csr[e];
        float4 h0 = h8_to_f4(((const float2*)(h + (size_t)s0 * 128))[lane]);
        ax += h0.x; ay += h0.y; az += h0.z; aw += h0.w;
    }
    for (; e + 8 <= end; e += 8) {
        int4 i0 = *(const int4*)(g_csr + e);
        int4 i1 = *(const int4*)(g_csr + e + 4);
        float2 r0 = ((const float2*)(h + (size_t)i0.x * 128))[lane];
        float2 r1 = ((const float2*)(h + (size_t)i0.y * 128))[lane];
        float2 r2 = ((const float2*)(h + (size_t)i0.z * 128))[lane];
        float2 r3 = ((const float2*)(h + (size_t)i0.w * 128))[lane];
        float2 r4 = ((const float2*)(h + (size_t)i1.x * 128))[lane];
        float2 r5 = ((const float2*)(h + (size_t)i1.y * 128))[lane];
        float2 r6 = ((const float2*)(h + (size_t)i1.z * 128))[lane];
        float2 r7 = ((const float2*)(h + (size_t)i1.w * 128))[lane];
        float4 p0 = pairsum_f4(r0, r1);
        float4 p1 = pairsum_f4(r2, r3);
        float4 p2 = pairsum_f4(r4, r5);
        float4 p3 = pairsum_f4(r6, r7);
        ax += (p0.x + p1.x) + (p2.x + p3.x);
        ay += (p0.y + p1.y) + (p2.y + p3.y);
        az += (p0.z + p1.z) + (p2.z + p3.z);
        aw += (p0.w + p1.w) + (p2.w + p3.w);
    }
    for (; e < end; e++) {
        int s0 = g_csr[e];
        float4 h0 = h8_to_f4(((const float2*)(h + (size_t)s0 * 128))[lane]);
        ax += h0.x; ay += h0.y; az += h0.z; aw += h0.w;
    }

    float4 hs = h8_to_f4(((const float2*)(h + (size_t)w * 128))[lane]);
    float4 bb = ((const float4*)b)[lane];
    float rx = fmaxf(dv * (ax + hs.x) + bb.x, 0.f);
    float ry = fmaxf(dv * (ay + hs.y) + bb.y, 0.f);
    float rz = fmaxf(dv * (az + hs.z) + bb.z, 0.f);
    float rw = fmaxf(dv * (aw + hs.w) + bb.w, 0.f);

    if (W4 == nullptr) {
        ((float2*)(g_a16 + (size_t)w * 128))[lane] = f4_to_h8(rx, ry, rz, rw);
    } else {
        float4 wv = ((const float4*)W4)[lane];
        float s = rx * wv.x + ry * wv.y + rz * wv.z + rw * wv.w;
#pragma unroll
        for (int o = 16; o; o >>= 1) s += __shfl_xor_sync(0xFFFFFFFFu, s, o);
        if (lane == 0) g_t[w] = dv * s;
    }
}

__global__ void final_agg_k(const float* __restrict__ b4, float* __restrict__ out, int M)
{
    int v = blockIdx.x * blockDim.x + threadIdx.x;
    if (v >= M) return;
    float dv = g_dis[v];
    int beg = g_off[v], end = g_off[v + 1];
    float s = 0.f;
    int e = beg;
    for (; e < end && (e & 3); e++) s += g_t[g_csr[e]];
    for (; e + 4 <= end; e += 4) {
        int4 i0 = *(const int4*)(g_csr + e);
        s += g_t[i0.x] + g_t[i0.y] + g_t[i0.z] + g_t[i0.w];
    }
    for (; e < end; e++) s += g_t[g_csr[e]];
    out[v] = dv * (s + g_t[v]) + b4[0];
}

// ---------------- launch ----------------
extern "C" void kernel_launch(void* const* d_in, const int* in_sizes, int n_in,
                              void* d_out, int out_size)
{
    const float* x  = (const float*)d_in[0];
    const int*   ei = (const int*)d_in[1];
    const float* W1 = (const float*)d_in[2]; const float* b1 = (const float*)d_in[3];
    const float* W2 = (const float*)d_in[4]; const float* b2 = (const float*)d_in[5];
    const float* W3 = (const float*)d_in[6]; const float* b3 = (const float*)d_in[7];
    const float* W4 = (const float*)d_in[8]; const float* b4 = (const float*)d_in[9];

    int N = in_sizes[0] / 128;   // 50000
    int E = in_sizes[1] / 2;     // 1600000
    float* out = (float*)d_out;

    int nb = (N + SCAN_B - 1) / SCAN_B;      // 49

    // graph preprocessing
    zero_cnt_k <<<(N + 255) / 256, 256>>>(N);
    hist_dst_k <<<(E / 4 + 255) / 256, 256>>>(ei, E);
    scan1_k    <<<nb, SCAN_B>>>(N);
    scan3_k    <<<(N + 255) / 256, 256>>>(N, nb);
    build_csr_k<<<(E / 4 + 255) / 256, 256>>>(ei, E);

    int gemm_blocks = (N + 127) / 128;
    int agg_blocks  = (N * 32 + 255) / 256;

    gemm_fp16_k<<<gemm_blocks, 256>>>(x, W1, N, 0);
    agg128_k   <<<agg_blocks, 256>>>(b1, N, nullptr);

    gemm_fp16_k<<<gemm_blocks, 256>>>(x, W2, N, 1);
    agg128_k   <<<agg_blocks, 256>>>(b2, N, nullptr);

    gemm_fp16_k<<<gemm_blocks, 256>>>(x, W3, N, 1);
    agg128_k   <<<agg_blocks, 256>>>(b3, N, W4);

    final_agg_k<<<(N + 255) / 256, 256>>>(b4, out, N);
}

// round 9
// speedup vs baseline: 2.7127x; 1.0324x over previous
#include <cuda_runtime.h>
#include <cuda_fp16.h>
#include <cstddef>

#define NN_MAX 50000
#define EE_MAX 1600000
#define SCAN_B 1024
#define NB_MAX 64

// -------- scratch (device globals; no allocation allowed) --------
__device__ __align__(16) float  g_dis[NN_MAX];      // 1/sqrt(1+in_deg)
__device__ int    g_cnt[NN_MAX];
__device__ int    g_off[NN_MAX + 1];
__device__ int    g_sl[NN_MAX];                     // block-local exclusive scan
__device__ int    g_bsum[NB_MAX];                   // per-block totals
__device__ __align__(16) int g_slot[EE_MAX];        // per-edge slot within dst bucket
__device__ __align__(16) int g_csr[EE_MAX];
__device__ __align__(16) __half g_h16[(size_t)NN_MAX * 128];  // post-GEMM, PRE-SCALED by dis[row]
__device__ __align__(16) __half g_a16[(size_t)NN_MAX * 128];  // post-agg activations
__device__ float  g_t[NN_MAX];                      // final scalar projection, PRE-SCALED

// ---------------- helpers ----------------
__device__ __forceinline__ float4 h8_to_f4(float2 raw) {
    __half2 ha = *reinterpret_cast<__half2*>(&raw.x);
    __half2 hb = *reinterpret_cast<__half2*>(&raw.y);
    float2 fa = __half22float2(ha), fb = __half22float2(hb);
    return make_float4(fa.x, fa.y, fb.x, fb.y);
}
__device__ __forceinline__ float2 f4_to_h8(float x, float y, float z, float w) {
    __half2 h0 = __floats2half2_rn(x, y), h1 = __floats2half2_rn(z, w);
    float2 o;
    o.x = *reinterpret_cast<float*>(&h0);
    o.y = *reinterpret_cast<float*>(&h1);
    return o;
}
__device__ __forceinline__ float4 pairsum_f4(float2 ra, float2 rb) {
    __half2 alo = *reinterpret_cast<__half2*>(&ra.x);
    __half2 ahi = *reinterpret_cast<__half2*>(&ra.y);
    __half2 blo = *reinterpret_cast<__half2*>(&rb.x);
    __half2 bhi = *reinterpret_cast<__half2*>(&rb.y);
    __half2 slo = __hadd2(alo, blo);
    __half2 shi = __hadd2(ahi, bhi);
    float2 fa = __half22float2(slo), fb = __half22float2(shi);
    return make_float4(fa.x, fa.y, fb.x, fb.y);
}

// ---------------- graph preprocessing ----------------
__global__ void zero_cnt_k(int n) {
    int i = blockIdx.x * blockDim.x + threadIdx.x;
    if (i < n) g_cnt[i] = 0;
}

// 4 edges per thread; records each edge's slot within its dst bucket
__global__ void hist_dst_k(const int* __restrict__ ei, int E) {
    int t = blockIdx.x * blockDim.x + threadIdx.x;
    int e = t * 4;
    if (e + 3 < E) {
        int4 d = *(const int4*)(ei + E + e);
        int p0 = atomicAdd(&g_cnt[d.x], 1);
        int p1 = atomicAdd(&g_cnt[d.y], 1);
        int p2 = atomicAdd(&g_cnt[d.z], 1);
        int p3 = atomicAdd(&g_cnt[d.w], 1);
        *(int4*)(g_slot + e) = make_int4(p0, p1, p2, p3);
    } else {
        for (; e < E; e++) g_slot[e] = atomicAdd(&g_cnt[ei[E + e]], 1);
    }
}

// block-local scan + per-block totals
__global__ void scan1_k(int n) {
    __shared__ int sh[SCAN_B];
    int t = threadIdx.x;
    int i = blockIdx.x * SCAN_B + t;
    int v = (i < n) ? g_cnt[i] : 0;
    sh[t] = v;
    __syncthreads();
    for (int d = 1; d < SCAN_B; d <<= 1) {
        int u = (t >= d) ? sh[t - d] : 0;
        __syncthreads();
        sh[t] += u;
        __syncthreads();
    }
    if (i < n) g_sl[i] = sh[t] - v;            // exclusive
    if (t == SCAN_B - 1) g_bsum[blockIdx.x] = sh[t];
}

// combine: every block redundantly scans the (<=64) block totals in smem
__global__ void scan3_k(int n, int nb) {
    __shared__ int sh[NB_MAX];
    int t = threadIdx.x;
    if (t < NB_MAX) sh[t] = (t < nb) ? g_bsum[t] : 0;
    __syncthreads();
    for (int d = 1; d < NB_MAX; d <<= 1) {
        int u = (t < NB_MAX && t >= d) ? sh[t - d] : 0;
        __syncthreads();
        if (t < NB_MAX) sh[t] += u;
        __syncthreads();
    }
    int i = blockIdx.x * blockDim.x + t;
    if (i >= n) return;
    int bidx = i >> 10;
    int boff = (bidx > 0) ? sh[bidx - 1] : 0;
    int off = g_sl[i] + boff;
    g_off[i] = off;
    int c = g_cnt[i];
    g_dis[i] = rsqrtf(1.0f + (float)c);
    if (i == n - 1) g_off[n] = off + c;
}

// atomic-free CSR fill: csr[off[dst] + slot] = src
__global__ void build_csr_k(const int* __restrict__ ei, int E) {
    int t = blockIdx.x * blockDim.x + threadIdx.x;
    int e = t * 4;
    if (e + 3 < E) {
        int4 s  = *(const int4*)(ei + e);
        int4 d  = *(const int4*)(ei + E + e);
        int4 sl = *(const int4*)(g_slot + e);
        g_csr[g_off[d.x] + sl.x] = s.x;
        g_csr[g_off[d.y] + sl.y] = s.y;
        g_csr[g_off[d.z] + sl.z] = s.z;
        g_csr[g_off[d.w] + sl.w] = s.w;
    } else {
        for (; e < E; e++) g_csr[g_off[ei[E + e]] + g_slot[e]] = ei[e];
    }
}

// ---------------- fp16 tensor-core GEMM: g_h16[M,:] = dis[row] * (A @ W) ------
__global__ __launch_bounds__(256, 2)
void gemm_fp16_k(const float* __restrict__ Ax, const float* __restrict__ W,
                 int M, int use_ga)
{
    __shared__ __align__(16) __half2 As2[128][20];
    __shared__ __align__(16) __half2 Bs2[16][136];

    int tid  = threadIdx.x;
    int wid  = tid >> 5;
    int lane = tid & 31;
    int g    = lane >> 2;
    int tig  = lane & 3;
    int warp_m = wid & 3;
    int warp_n = wid >> 2;
    int row0 = blockIdx.x * 128;

    float acc[2][8][4];
#pragma unroll
    for (int mf = 0; mf < 2; mf++)
#pragma unroll
        for (int nf = 0; nf < 8; nf++)
#pragma unroll
            for (int i = 0; i < 4; i++) acc[mf][nf][i] = 0.f;

    for (int kb = 0; kb < 128; kb += 32) {
        if (use_ga) {
            const __half* A16 = g_a16;
#pragma unroll
            for (int l = 0; l < 2; l++) {
                int idx = tid + l * 256;
                int r  = idx >> 2;
                int c8 = idx & 3;
                int gr = row0 + r;
                if (gr > M - 1) gr = M - 1;
                float4 raw = *(const float4*)(A16 + (size_t)gr * 128 + kb + c8 * 8);
                *(float4*)(&As2[r][c8 * 4]) = raw;
            }
        } else {
#pragma unroll
            for (int l = 0; l < 4; l++) {
                int idx = tid + l * 256;
                int r  = idx >> 3;
                int c4 = idx & 7;
                int gr = row0 + r;
                if (gr > M - 1) gr = M - 1;
                float4 v = *(const float4*)(Ax + (size_t)gr * 128 + kb + c4 * 4);
                As2[r][c4 * 2]     = __floats2half2_rn(v.x, v.y);
                As2[r][c4 * 2 + 1] = __floats2half2_rn(v.z, v.w);
            }
        }
#pragma unroll
        for (int l = 0; l < 2; l++) {
            int idx = tid + l * 256;
            int r  = idx >> 5;
            int c4 = idx & 31;
            const float* w0 = W + (size_t)(kb + 2 * r) * 128 + c4 * 4;
            float4 v0 = *(const float4*)w0;
            float4 v1 = *(const float4*)(w0 + 128);
            __half2 p0 = __floats2half2_rn(v0.x, v1.x);
            __half2 p1 = __floats2half2_rn(v0.y, v1.y);
            __half2 p2 = __floats2half2_rn(v0.z, v1.z);
            __half2 p3 = __floats2half2_rn(v0.w, v1.w);
            __half2* d = &Bs2[r][c4 * 4];
            d[0] = p0; d[1] = p1; d[2] = p2; d[3] = p3;
        }
        __syncthreads();

#pragma unroll
        for (int ks = 0; ks < 2; ks++) {
            int k0 = ks * 8;
            unsigned a[2][4];
#pragma unroll
            for (int mf = 0; mf < 2; mf++) {
                int rb = warp_m * 32 + mf * 16 + g;
                a[mf][0] = *(unsigned*)&As2[rb][k0 + tig];
                a[mf][1] = *(unsigned*)&As2[rb + 8][k0 + tig];
                a[mf][2] = *(unsigned*)&As2[rb][k0 + tig + 4];
                a[mf][3] = *(unsigned*)&As2[rb + 8][k0 + tig + 4];
            }
            unsigned b[8][2];
#pragma unroll
            for (int nf = 0; nf < 8; nf++) {
                int cb = warp_n * 64 + nf * 8 + g;
                b[nf][0] = *(unsigned*)&Bs2[k0 + tig][cb];
                b[nf][1] = *(unsigned*)&Bs2[k0 + tig + 4][cb];
            }
#pragma unroll
            for (int mf = 0; mf < 2; mf++)
#pragma unroll
                for (int nf = 0; nf < 8; nf++) {
                    asm volatile(
                        "mma.sync.aligned.m16n8k16.row.col.f32.f16.f16.f32 "
                        "{%0,%1,%2,%3}, {%4,%5,%6,%7}, {%8,%9}, {%0,%1,%2,%3};"
                        : "+f"(acc[mf][nf][0]), "+f"(acc[mf][nf][1]),
                          "+f"(acc[mf][nf][2]), "+f"(acc[mf][nf][3])
                        : "r"(a[mf][0]), "r"(a[mf][1]), "r"(a[mf][2]), "r"(a[mf][3]),
                          "r"(b[nf][0]), "r"(b[nf][1]));
                }
        }
        __syncthreads();
    }

#pragma unroll
    for (int mf = 0; mf < 2; mf++) {
        int rb = row0 + warp_m * 32 + mf * 16 + g;
        float d0 = (rb < M)     ? g_dis[rb]     : 0.f;
        float d1 = (rb + 8 < M) ? g_dis[rb + 8] : 0.f;
#pragma unroll
        for (int nf = 0; nf < 8; nf++) {
            int col = warp_n * 64 + nf * 8 + tig * 2;
            if (rb < M) {
                __half2 v = __floats2half2_rn(d0 * acc[mf][nf][0], d0 * acc[mf][nf][1]);
                *(__half2*)(g_h16 + (size_t)rb * 128 + col) = v;
            }
            if (rb + 8 < M) {
                __half2 v = __floats2half2_rn(d1 * acc[mf][nf][2], d1 * acc[mf][nf][3]);
                *(__half2*)(g_h16 + (size_t)(rb + 8) * 128 + col) = v;
            }
        }
    }
}

// ---------------- aggregation: warp per node, pure gather+add ----------------
__global__ void agg128_k(const float* __restrict__ b, int M,
                         const float* __restrict__ W4)
{
    int w = (blockIdx.x * blockDim.x + threadIdx.x) >> 5;
    if (w >= M) return;
    int lane = threadIdx.x & 31;
    const __half* __restrict__ h = g_h16;
    int beg = g_off[w], end = g_off[w + 1];
    float dv = g_dis[w];

    float ax = 0.f, ay = 0.f, az = 0.f, aw = 0.f;
    int e = beg;
    for (; e < end && (e & 3); e++) {
        int s0 = g_csr[e];
        float4 h0 = h8_to_f4(((const float2*)(h + (size_t)s0 * 128))[lane]);
        ax += h0.x; ay += h0.y; az += h0.z; aw += h0.w;
    }
    for (; e + 8 <= end; e += 8) {
        int4 i0 = *(const int4*)(g_csr + e);
        int4 i1 = *(const int4*)(g_csr + e + 4);
        float2 r0 = ((const float2*)(h + (size_t)i0.x * 128))[lane];
        float2 r1 = ((const float2*)(h + (size_t)i0.y * 128))[lane];
        float2 r2 = ((const float2*)(h + (size_t)i0.z * 128))[lane];
        float2 r3 = ((const float2*)(h + (size_t)i0.w * 128))[lane];
        float2 r4 = ((const float2*)(h + (size_t)i1.x * 128))[lane];
        float2 r5 = ((const float2*)(h + (size_t)i1.y * 128))[lane];
        float2 r6 = ((const float2*)(h + (size_t)i1.z * 128))[lane];
        float2 r7 = ((const float2*)(h + (size_t)i1.w * 128))[lane];
        float4 p0 = pairsum_f4(r0, r1);
        float4 p1 = pairsum_f4(r2, r3);
        float4 p2 = pairsum_f4(r4, r5);
        float4 p3 = pairsum_f4(r6, r7);
        ax += (p0.x + p1.x) + (p2.x + p3.x);
        ay += (p0.y + p1.y) + (p2.y + p3.y);
        az += (p0.z + p1.z) + (p2.z + p3.z);
        aw += (p0.w + p1.w) + (p2.w + p3.w);
    }
    for (; e < end; e++) {
        int s0 = g_csr[e];
        float4 h0 = h8_to_f4(((const float2*)(h + (size_t)s0 * 128))[lane]);
        ax += h0.x; ay += h0.y; az += h0.z; aw += h0.w;
    }

    float4 hs = h8_to_f4(((const float2*)(h + (size_t)w * 128))[lane]);
    float4 bb = ((const float4*)b)[lane];
    float rx = fmaxf(dv * (ax + hs.x) + bb.x, 0.f);
    float ry = fmaxf(dv * (ay + hs.y) + bb.y, 0.f);
    float rz = fmaxf(dv * (az + hs.z) + bb.z, 0.f);
    float rw = fmaxf(dv * (aw + hs.w) + bb.w, 0.f);

    if (W4 == nullptr) {
        ((float2*)(g_a16 + (size_t)w * 128))[lane] = f4_to_h8(rx, ry, rz, rw);
    } else {
        float4 wv = ((const float4*)W4)[lane];
        float s = rx * wv.x + ry * wv.y + rz * wv.z + rw * wv.w;
#pragma unroll
        for (int o = 16; o; o >>= 1) s += __shfl_xor_sync(0xFFFFFFFFu, s, o);
        if (lane == 0) g_t[w] = dv * s;
    }
}

__global__ void final_agg_k(const float* __restrict__ b4, float* __restrict__ out, int M)
{
    int v = blockIdx.x * blockDim.x + threadIdx.x;
    if (v >= M) return;
    float dv = g_dis[v];
    int beg = g_off[v], end = g_off[v + 1];
    float s = 0.f;
    int e = beg;
    for (; e < end && (e & 3); e++) s += g_t[g_csr[e]];
    for (; e + 4 <= end; e += 4) {
        int4 i0 = *(const int4*)(g_csr + e);
        s += g_t[i0.x] + g_t[i0.y] + g_t[i0.z] + g_t[i0.w];
    }
    for (; e < end; e++) s += g_t[g_csr[e]];
    out[v] = dv * (s + g_t[v]) + b4[0];
}

// ---------------- launch ----------------
extern "C" void kernel_launch(void* const* d_in, const int* in_sizes, int n_in,
                              void* d_out, int out_size)
{
    const float* x  = (const float*)d_in[0];
    const int*   ei = (const int*)d_in[1];
    const float* W1 = (const float*)d_in[2]; const float* b1 = (const float*)d_in[3];
    const float* W2 = (const float*)d_in[4]; const float* b2 = (const float*)d_in[5];
    const float* W3 = (const float*)d_in[6]; const float* b3 = (const float*)d_in[7];
    const float* W4 = (const float*)d_in[8]; const float* b4 = (const float*)d_in[9];

    int N = in_sizes[0] / 128;   // 50000
    int E = in_sizes[1] / 2;     // 1600000
    float* out = (float*)d_out;

    int nb = (N + SCAN_B - 1) / SCAN_B;      // 49

    // side stream + events (created once; no device memory involved)
    static cudaStream_t s_pre = nullptr;
    static cudaEvent_t ev_fork = nullptr, ev_dis = nullptr, ev_csr = nullptr;
    if (s_pre == nullptr) {
        cudaStreamCreateWithFlags(&s_pre, cudaStreamNonBlocking);
        cudaEventCreateWithFlags(&ev_fork, cudaEventDisableTiming);
        cudaEventCreateWithFlags(&ev_dis,  cudaEventDisableTiming);
        cudaEventCreateWithFlags(&ev_csr,  cudaEventDisableTiming);
    }

    // fork: preprocessing on s_pre
    cudaEventRecord(ev_fork, 0);
    cudaStreamWaitEvent(s_pre, ev_fork, 0);
    zero_cnt_k <<<(N + 255) / 256, 256, 0, s_pre>>>(N);
    hist_dst_k <<<(E / 4 + 255) / 256, 256, 0, s_pre>>>(ei, E);
    scan1_k    <<<nb, SCAN_B, 0, s_pre>>>(N);
    scan3_k    <<<(N + 255) / 256, 256, 0, s_pre>>>(N, nb);
    cudaEventRecord(ev_dis, s_pre);                     // g_dis/g_off ready
    build_csr_k<<<(E / 4 + 255) / 256, 256, 0, s_pre>>>(ei, E);
    cudaEventRecord(ev_csr, s_pre);                     // CSR ready

    int gemm_blocks = (N + 127) / 128;
    int agg_blocks  = (N * 32 + 255) / 256;

    // GEMM-1 needs g_dis (epilogue) but not the CSR: overlaps with build_csr
    cudaStreamWaitEvent(0, ev_dis, 0);
    gemm_fp16_k<<<gemm_blocks, 256>>>(x, W1, N, 0);
    cudaStreamWaitEvent(0, ev_csr, 0);                  // join before aggregation
    agg128_k   <<<agg_blocks, 256>>>(b1, N, nullptr);

    gemm_fp16_k<<<gemm_blocks, 256>>>(x, W2, N, 1);
    agg128_k   <<<agg_blocks, 256>>>(b2, N, nullptr);

    gemm_fp16_k<<<gemm_blocks, 256>>>(x, W3, N, 1);
    agg128_k   <<<agg_blocks, 256>>>(b3, N, W4);

    final_agg_k<<<(N + 255) / 256, 256>>>(b4, out, N);
}